// round 10
// baseline (speedup 1.0000x reference)
#include <cuda_runtime.h>
#include <cuda_bf16.h>
#include <math.h>

// Problem constants
#define BB 16
#define LL 2048
#define DIN 8
#define HH 256
#define NN 64
#define NLAYERS 4
#define GM (BB*LL)      // 32768 rows
#define GK HH           // 256
#define GN (2*HH)       // 512
#define NC 16           // time chunks
#define TT (LL/NC)      // 128
#define MM (BB*NC)      // 256 chunk-columns

typedef unsigned long long ull;
typedef unsigned int u32;

// Scratch (device globals)
__device__ float g_x[(size_t)GM*HH];                       // activations (row,h)
__device__ float g_s[(size_t)GM*HH];                       // pre-LN (row,h)
__device__ __nv_bfloat16 g_gh[(size_t)GM*HH];              // gelu out hi (row,h)
__device__ __nv_bfloat16 g_gl[(size_t)GM*HH];              // gelu out lo
__device__ __nv_bfloat16 g_wh[(size_t)NLAYERS*GN*GK];      // GLU W hi
__device__ __nv_bfloat16 g_wl[(size_t)NLAYERS*GN*GK];      // GLU W lo
__device__ __nv_bfloat16 g_Xh[(size_t)HH*MM*256];          // X=[u;z0] hi (h,m,k)
__device__ __nv_bfloat16 g_Xl[(size_t)HH*MM*256];          // X lo
__device__ __nv_bfloat16 g_GAh[(size_t)NLAYERS*HH*128*256];// [K|V] hi (l,h,r,k)
__device__ __nv_bfloat16 g_GAl[(size_t)NLAYERS*HH*128*256];
__device__ __nv_bfloat16 g_GWh[(size_t)NLAYERS*HH*128*128];// W hi (l,h,i,s)
__device__ __nv_bfloat16 g_GWl[(size_t)NLAYERS*HH*128*128];
__device__ float g_zc[(size_t)HH*128*MM];                  // Zend0 (h,i,m)
__device__ float g_y[(size_t)HH*TT*MM];                    // conv out (h,t,m)

__device__ __forceinline__ void bsplit(float v, __nv_bfloat16& h, __nv_bfloat16& l) {
    h = __float2bfloat16_rn(v);
    l = __float2bfloat16_rn(v - __bfloat162float(h));
}

// ---------------------------------------------------------------------------
// enc_fused: x @ enc_w^T + b -> g_x (row,h)  AND X (h,m,t) bf16 hi/lo.
//   block = 32 rows, 256 threads; grid GM/32.
// ---------------------------------------------------------------------------
__global__ void __launch_bounds__(256) enc_fused_kernel(
    const float* __restrict__ x,
    const float* __restrict__ w,
    const float* __restrict__ b)
{
    __shared__ float ys[32][260];
    __shared__ float xr[32][8];
    const int tid = threadIdx.x, wi = tid >> 5, lane = tid & 31;
    const int r0 = blockIdx.x*32;

    xr[tid >> 3][tid & 7] = x[(size_t)(r0 + (tid >> 3))*DIN + (tid & 7)];
    __syncthreads();

    #pragma unroll
    for (int it = 0; it < 4; it++) {
        int rl = wi + it*8;
        size_t row = (size_t)(r0 + rl);
        #pragma unroll
        for (int q = 0; q < 8; q++) {
            int h = lane + q*32;
            float s = b[h];
            #pragma unroll
            for (int k = 0; k < DIN; k++)
                s = fmaf(xr[rl][k], w[h*DIN + k], s);
            g_x[row*HH + h] = s;
            ys[rl][h] = s;
        }
    }
    __syncthreads();

    const int h = tid;
    const int m = r0 >> 7, t0 = r0 & 127;
    union P4 { __nv_bfloat16 b[4]; ull u; };
    size_t dst = (size_t)h*((size_t)MM*256) + (size_t)m*256 + t0;
    #pragma unroll
    for (int j4 = 0; j4 < 8; j4++) {
        P4 ph, pl;
        #pragma unroll
        for (int i = 0; i < 4; i++) bsplit(ys[j4*4 + i][h], ph.b[i], pl.b[i]);
        *(ull*)(g_Xh + dst + j4*4) = ph.u;
        *(ull*)(g_Xl + dst + j4*4) = pl.u;
    }
}

// ---------------------------------------------------------------------------
// One-shot GLU W -> bf16 hi/lo split
// ---------------------------------------------------------------------------
__global__ void wconv_kernel(const float* __restrict__ W)
{
    size_t i = (size_t)blockIdx.x*256 + threadIdx.x;
    float w = W[i];
    bsplit(w, g_wh[i], g_wl[i]);
}

// ---------------------------------------------------------------------------
__device__ __forceinline__ void s4_lambda(
    const float* log_dt, const float* logA_re, const float* A_im,
    int h, int n, float& Lr, float& Li, float& are, float& aim)
{
    float dt = expf(log_dt[h]);
    are = -expf(logA_re[h*NN + n]);
    aim = A_im[h*NN + n];
    float er = expf(dt*are);
    float dim = dt*aim;
    Lr = er*cosf(dim);
    Li = er*sinf(dim);
}

// ---------------------------------------------------------------------------
// genG_all: per-(layer,channel) G_A=[K|V] (128x256), G_W (128x128), bf16 hi/lo.
// ---------------------------------------------------------------------------
__global__ void __launch_bounds__(128) genG_all_kernel(
    const float* __restrict__ log_dt_a,
    const float* __restrict__ logA_a,
    const float* __restrict__ A_im_a,
    const float* __restrict__ C_re_a,
    const float* __restrict__ C_im_a,
    const float* __restrict__ Dp_a)
{
    const int h = blockIdx.x;
    const int l = blockIdx.y;
    const int t = threadIdx.x;
    const float* log_dt = log_dt_a + l*HH;
    const float* logA_re = logA_a + (size_t)l*HH*NN;
    const float* A_im = A_im_a + (size_t)l*HH*NN;
    const float* C_re = C_re_a + (size_t)l*HH*NN;
    const float* C_im = C_im_a + (size_t)l*HH*NN;

    __shared__ float s_cr[64], s_ci[64], s_lr[64], s_li[64];
    __shared__ float s_pr[64][33], s_pi[64][33];
    __shared__ float s_k[128];

    float pr = 1.f, pi = 0.f;
    if (t < 64) {
        float are, aim, Lr, Li;
        s4_lambda(log_dt, logA_re, A_im, h, t, Lr, Li, are, aim);
        s_lr[t] = Lr; s_li[t] = Li;
        float Cre = C_re[h*NN + t], Cim = C_im[h*NN + t];
        float nr = Lr - 1.f, ni = Li;
        float tr = Cre*nr - Cim*ni, ti = Cre*ni + Cim*nr;
        float inv = 2.f/(are*are + aim*aim);
        s_cr[t] =  inv*(tr*are + ti*aim);
        s_ci[t] = -inv*(ti*are - tr*aim);
    }
    __syncthreads();
    const float Dh = Dp_a[l*HH + h];
    __nv_bfloat16* GAh = g_GAh + ((size_t)l*HH + h)*128*256;
    __nv_bfloat16* GAl = g_GAl + ((size_t)l*HH + h)*128*256;
    __nv_bfloat16* GWh = g_GWh + ((size_t)l*HH + h)*128*128;
    __nv_bfloat16* GWl = g_GWl + ((size_t)l*HH + h)*128*128;

    for (int cd = 0; cd < 4; cd++) {
        if (t < 64) {
            float Lr = s_lr[t], Li = s_li[t];
            #pragma unroll
            for (int dd = 0; dd < 32; dd++) {
                s_pr[t][dd] = pr; s_pi[t][dd] = pi;
                float npr = pr*Lr - pi*Li;
                float npi = pr*Li + pi*Lr;
                pr = npr; pi = npi;
            }
        }
        __syncthreads();
        {
            int dd = t >> 2, q = t & 3;
            float part = 0.f;
            for (int n = q*16; n < q*16 + 16; n++)
                part += s_cr[n]*s_pr[n][dd] + s_ci[n]*s_pi[n][dd];
            part += __shfl_xor_sync(0xffffffffu, part, 1);
            part += __shfl_xor_sync(0xffffffffu, part, 2);
            int d = cd*32 + dd;
            if (q == 0) s_k[d] = part + (d == 0 ? Dh : 0.f);
        }
        for (int dd = 0; dd < 32; dd++) {
            int d = cd*32 + dd, r = d - 1;
            if (r >= 0) {
                float v;
                if (t < 64)
                    v = s_cr[t]*s_pr[t][dd] + s_ci[t]*s_pi[t][dd];
                else {
                    int j = t - 64;
                    v = s_ci[j]*s_pr[j][dd] - s_cr[j]*s_pi[j][dd];
                }
                __nv_bfloat16 hb, lb; bsplit(v, hb, lb);
                GAh[r*256 + 128 + t] = hb;
                GAl[r*256 + 128 + t] = lb;
            }
        }
        for (int p = 0; p < 32; p++) {
            int row = p*4 + (t >> 5);
            int sc = t & 31;
            int s = 96 - cd*32 + sc;
            int dd = 31 - sc;
            float v = (row < 64) ? s_pr[row][dd] : s_pi[row-64][dd];
            __nv_bfloat16 hb, lb; bsplit(v, hb, lb);
            GWh[row*128 + s] = hb;
            GWl[row*128 + s] = lb;
        }
        __syncthreads();
    }
    if (t < 64) { s_pr[t][0] = pr; s_pi[t][0] = pi; }
    __syncthreads();
    {
        float v;
        if (t < 64)
            v = s_cr[t]*s_pr[t][0] + s_ci[t]*s_pi[t][0];
        else {
            int j = t - 64;
            v = s_ci[j]*s_pr[j][0] - s_cr[j]*s_pi[j][0];
        }
        __nv_bfloat16 hb, lb; bsplit(v, hb, lb);
        GAh[127*256 + 128 + t] = hb;
        GAl[127*256 + 128 + t] = lb;
    }
    for (int r = 0; r < 128; r++) {
        float v = (t <= r) ? s_k[r - t] : 0.f;
        __nv_bfloat16 hb, lb; bsplit(v, hb, lb);
        GAh[r*256 + t] = hb;
        GAl[r*256 + t] = lb;
    }
}

// ---------------------------------------------------------------------------
// scanfix: compose Zend0 across chunks; write z0 (bf16 hi/lo) into X rows 128+
// ---------------------------------------------------------------------------
__global__ void __launch_bounds__(256) scanfix_kernel(
    const float* __restrict__ log_dt,
    const float* __restrict__ logA_re,
    const float* __restrict__ A_im)
{
    int gid = blockIdx.x*256 + threadIdx.x;
    int n = gid & 63, h = (gid >> 6) & 255, b = gid >> 14;

    float Lr, Li, are, aim;
    s4_lambda(log_dt, logA_re, A_im, h, n, Lr, Li, are, aim);
    #pragma unroll
    for (int s = 0; s < 7; s++) {
        float nr = Lr*Lr - Li*Li, ni = 2.f*Lr*Li;
        Lr = nr; Li = ni;
    }

    const float* zcre = g_zc + (size_t)h*128*MM + n*MM;
    const float* zcim = zcre + 64*MM;
    __nv_bfloat16* Xh = g_Xh + (size_t)h*MM*256;
    __nv_bfloat16* Xl = g_Xl + (size_t)h*MM*256;

    float cr = 0.f, ci = 0.f;
    #pragma unroll
    for (int c = 0; c < NC; c++) {
        int m = b*16 + c;
        __nv_bfloat16 hb, lb;
        bsplit(cr, hb, lb);
        Xh[(size_t)m*256 + 128 + n] = hb; Xl[(size_t)m*256 + 128 + n] = lb;
        bsplit(ci, hb, lb);
        Xh[(size_t)m*256 + 192 + n] = hb; Xl[(size_t)m*256 + 192 + n] = lb;
        float zr = zcre[m], zi = zcim[m];
        float nr = Lr*cr - Li*ci + zr;
        float ni = Lr*ci + Li*cr + zi;
        cr = nr; ci = ni;
    }
}

// ---------------------------------------------------------------------------
// GEMM building blocks (mma.sync path — sm_100 plain target)
// ---------------------------------------------------------------------------
__device__ __forceinline__ void cp16(u32 dst, const void* src) {
    asm volatile("cp.async.cg.shared.global [%0], [%1], 16;" :: "r"(dst), "l"(src));
}
__device__ __forceinline__ void ldsm4(u32& r0, u32& r1, u32& r2, u32& r3, u32 addr) {
    asm volatile("ldmatrix.sync.aligned.m8n8.x4.shared.b16 {%0,%1,%2,%3},[%4];"
                 : "=r"(r0), "=r"(r1), "=r"(r2), "=r"(r3) : "r"(addr));
}
__device__ __forceinline__ void mma_bf16(float* d, const u32* a, const u32* b) {
    asm volatile(
        "mma.sync.aligned.m16n8k16.row.col.f32.bf16.bf16.f32 "
        "{%0,%1,%2,%3},{%4,%5,%6,%7},{%8,%9},{%0,%1,%2,%3};"
        : "+f"(d[0]), "+f"(d[1]), "+f"(d[2]), "+f"(d[3])
        : "r"(a[0]), "r"(a[1]), "r"(a[2]), "r"(a[3]), "r"(b[0]), "r"(b[1]));
}

// Stage layout: Ah 0 | Al 8K | Bh 16K | Bl 20K ; stage stride 24K; 2 stages = 48K
#define STG2 24576

// ---------------------------------------------------------------------------
// gemm_s4: per-channel bf16x3 (pass1: Zend0 = G_W*U, K=128; pass2: Y = G_A*X, K=256)
// ---------------------------------------------------------------------------
__global__ void __launch_bounds__(256) gemm_s4_kernel(int pass, int l)
{
    __shared__ __align__(128) char smem_buf[2*STG2];
    const int h  = blockIdx.y;
    const int mt = blockIdx.x;
    const int tid = threadIdx.x, lane = tid & 31, w = tid >> 5;
    const int wm = w & 3, wn = w >> 2;

    const int NK = (pass == 1) ? 128 : 256;
    const __nv_bfloat16* Ahp = (pass == 1) ? g_GWh + ((size_t)l*HH + h)*128*128
                                           : g_GAh + ((size_t)l*HH + h)*128*256;
    const __nv_bfloat16* Alp = (pass == 1) ? g_GWl + ((size_t)l*HH + h)*128*128
                                           : g_GAl + ((size_t)l*HH + h)*128*256;
    const __nv_bfloat16* Bhp = g_Xh + (size_t)h*MM*256;
    const __nv_bfloat16* Blp = g_Xl + (size_t)h*MM*256;
    float* outp = ((pass == 1) ? g_zc : g_y) + (size_t)h*128*MM;

    const int nch = NK/32;
    const u32 smem_base = (u32)__cvta_generic_to_shared(smem_buf);

    float acc[2][4][4];
    #pragma unroll
    for (int mi = 0; mi < 2; mi++)
        #pragma unroll
        for (int ni = 0; ni < 4; ni++)
            #pragma unroll
            for (int r = 0; r < 4; r++) acc[mi][ni][r] = 0.f;

    auto load_chunk = [&](int kc, int stage) {
        int k0 = kc*32;
        u32 base = smem_base + stage*STG2;
        #pragma unroll
        for (int i = 0; i < 2; i++) {
            int gid = i*256 + tid;
            int row = gid >> 2, g = gid & 3;
            int pg = g ^ ((row >> 1) & 3);
            cp16(base + row*64 + pg*16,        Ahp + (size_t)row*NK + k0 + g*8);
            cp16(base + 8192 + row*64 + pg*16, Alp + (size_t)row*NK + k0 + g*8);
        }
        {
            int row = tid >> 2, g = tid & 3;
            int pg = g ^ ((row >> 1) & 3);
            cp16(base + 16384 + row*64 + pg*16, Bhp + (size_t)(mt*64 + row)*256 + k0 + g*8);
            cp16(base + 20480 + row*64 + pg*16, Blp + (size_t)(mt*64 + row)*256 + k0 + g*8);
        }
    };

    load_chunk(0, 0);
    asm volatile("cp.async.commit_group;");

    for (int kc = 0; kc < nch; kc++) {
        if (kc + 1 < nch) load_chunk(kc + 1, (kc + 1) & 1);
        asm volatile("cp.async.commit_group;");
        asm volatile("cp.async.wait_group 1;");
        __syncthreads();

        const u32 ab  = smem_base + (kc & 1)*STG2;
        const u32 alb = ab + 8192, bhb = ab + 16384, blb = ab + 20480;

        #pragma unroll
        for (int ks = 0; ks < 2; ks++) {
            const int grp = lane >> 3, rh = lane & 7;
            u32 ah[2][4], al[2][4];
            #pragma unroll
            for (int mi = 0; mi < 2; mi++) {
                int row = wm*32 + mi*16 + rh + (grp & 1)*8;
                int kg  = 2*ks + (grp >> 1);
                u32 off = row*64 + ((kg ^ ((row >> 1) & 3))*16);
                ldsm4(ah[mi][0], ah[mi][1], ah[mi][2], ah[mi][3], ab + off);
                ldsm4(al[mi][0], al[mi][1], al[mi][2], al[mi][3], alb + off);
            }
            u32 bh[4][2], bl[4][2];
            #pragma unroll
            for (int nf = 0; nf < 2; nf++) {
                int row = wn*32 + nf*16 + rh + (grp >> 1)*8;
                int kg  = 2*ks + (grp & 1);
                u32 off = row*64 + ((kg ^ ((row >> 1) & 3))*16);
                u32 r0, r1, r2, r3;
                ldsm4(r0, r1, r2, r3, bhb + off);
                bh[nf*2][0] = r0; bh[nf*2][1] = r1;
                bh[nf*2+1][0] = r2; bh[nf*2+1][1] = r3;
                ldsm4(r0, r1, r2, r3, blb + off);
                bl[nf*2][0] = r0; bl[nf*2][1] = r1;
                bl[nf*2+1][0] = r2; bl[nf*2+1][1] = r3;
            }
            #pragma unroll
            for (int mi = 0; mi < 2; mi++)
                #pragma unroll
                for (int ni = 0; ni < 4; ni++) {
                    mma_bf16(acc[mi][ni], ah[mi], bh[ni]);
                    mma_bf16(acc[mi][ni], al[mi], bh[ni]);
                    mma_bf16(acc[mi][ni], ah[mi], bl[ni]);
                }
        }
        __syncthreads();
    }

    const int lq = lane >> 2, lc = lane & 3;
    #pragma unroll
    for (int mi = 0; mi < 2; mi++) {
        #pragma unroll
        for (int ni = 0; ni < 4; ni++) {
            int row = wm*32 + mi*16 + lq;
            int col = mt*64 + wn*32 + ni*8 + lc*2;
            float2 v0; v0.x = acc[mi][ni][0]; v0.y = acc[mi][ni][1];
            float2 v1; v1.x = acc[mi][ni][2]; v1.y = acc[mi][ni][3];
            *(float2*)(outp + (size_t)row*MM + col) = v0;
            *(float2*)(outp + (size_t)(row+8)*MM + col) = v1;
        }
    }
}

// ---------------------------------------------------------------------------
// backT: g_y (h,t,m) fp32 -> gelu -> g_gh/g_gl (row,h) bf16 hi/lo
// ---------------------------------------------------------------------------
__global__ void __launch_bounds__(256) backT_kernel()
{
    const int m0 = blockIdx.x*32, t0 = blockIdx.y*8, h0 = blockIdx.z*32;
    __shared__ float sB[256][33];
    const int tid = threadIdx.x, w = tid >> 5, lane = tid & 31;

    for (int i = 0; i < 32; i++) {
        int seg = w*32 + i;
        int hh = seg >> 3, tt = seg & 7;
        float v = g_y[(size_t)(h0+hh)*TT*MM + (size_t)(t0+tt)*MM + m0 + lane];
        sB[tt*32 + lane][hh] = v;
    }
    __syncthreads();
    for (int i = 0; i < 32; i++) {
        int pair = w*32 + i;
        int mm = pair >> 3, tt = pair & 7;
        int m = m0 + mm;
        int b = m >> 4, cc = m & 15;
        size_t row = (size_t)b*LL + cc*TT + t0 + tt;
        float yv = sB[tt*32 + mm][lane];
        float gv = 0.5f*yv*(1.0f + erff(yv*0.70710678118654752f));
        __nv_bfloat16 hb, lb; bsplit(gv, hb, lb);
        g_gh[row*HH + h0 + lane] = hb;
        g_gl[row*HH + h0 + lane] = lb;
    }
}

// ---------------------------------------------------------------------------
// GLU GEMM (R8-proven): bf16x3, 128m x 64 gemm-cols, static 48KB smem,
// fused GLU+bias+residual. 8 warps = 4m x 2n; warp tile 32m x 32n.
// ---------------------------------------------------------------------------
__global__ void __launch_bounds__(256) gemm_glu_kernel(int l, const float* __restrict__ bias)
{
    __shared__ __align__(128) char smem_buf[2*STG2];

    const int m0  = blockIdx.y * 128;
    const int nb  = blockIdx.x;
    const int tid = threadIdx.x;
    const int lane = tid & 31, w = tid >> 5;
    const int wm = w & 3;
    const int wn = w >> 2;

    const __nv_bfloat16* Whp = g_wh + (size_t)l*GN*GK;
    const __nv_bfloat16* Wlp = g_wl + (size_t)l*GN*GK;

    const u32 smem_base = (u32)__cvta_generic_to_shared(smem_buf);

    float acc[2][4][4];
    #pragma unroll
    for (int mi = 0; mi < 2; mi++)
        #pragma unroll
        for (int ni = 0; ni < 4; ni++)
            #pragma unroll
            for (int r = 0; r < 4; r++) acc[mi][ni][r] = 0.f;

    auto load_chunk = [&](int kc, int stage) {
        int k0 = kc*32;
        u32 base = smem_base + stage*STG2;
        #pragma unroll
        for (int i = 0; i < 2; i++) {
            int gid = i*256 + tid;
            int row = gid >> 2, g = gid & 3;
            int pg = g ^ ((row >> 1) & 3);
            cp16(base + row*64 + pg*16,        g_gh + (size_t)(m0 + row)*GK + k0 + g*8);
            cp16(base + 8192 + row*64 + pg*16, g_gl + (size_t)(m0 + row)*GK + k0 + g*8);
        }
        {
            int row = tid >> 2, g = tid & 3;
            int pg = g ^ ((row >> 1) & 3);
            int wr = nb*32 + (row >> 1) + (row & 1)*256;
            cp16(base + 16384 + row*64 + pg*16, Whp + (size_t)wr*GK + k0 + g*8);
            cp16(base + 20480 + row*64 + pg*16, Wlp + (size_t)wr*GK + k0 + g*8);
        }
    };

    load_chunk(0, 0);
    asm volatile("cp.async.commit_group;");

    #pragma unroll 1
    for (int kc = 0; kc < 8; kc++) {
        if (kc + 1 < 8) load_chunk(kc + 1, (kc + 1) & 1);
        asm volatile("cp.async.commit_group;");
        asm volatile("cp.async.wait_group 1;");
        __syncthreads();

        const u32 ab  = smem_base + (kc & 1)*STG2;
        const u32 alb = ab + 8192, bhb = ab + 16384, blb = ab + 20480;

        #pragma unroll
        for (int ks = 0; ks < 2; ks++) {
            const int grp = lane >> 3, rh = lane & 7;
            u32 ah[2][4], al[2][4];
            #pragma unroll
            for (int mi = 0; mi < 2; mi++) {
                int row = wm*32 + mi*16 + rh + (grp & 1)*8;
                int kg  = 2*ks + (grp >> 1);
                u32 off = row*64 + ((kg ^ ((row >> 1) & 3))*16);
                ldsm4(ah[mi][0], ah[mi][1], ah[mi][2], ah[mi][3], ab + off);
                ldsm4(al[mi][0], al[mi][1], al[mi][2], al[mi][3], alb + off);
            }
            u32 bh[4][2], bl[4][2];
            #pragma unroll
            for (int nf = 0; nf < 2; nf++) {
                int row = wn*32 + nf*16 + rh + (grp >> 1)*8;
                int kg  = 2*ks + (grp & 1);
                u32 off = row*64 + ((kg ^ ((row >> 1) & 3))*16);
                u32 r0, r1, r2, r3;
                ldsm4(r0, r1, r2, r3, bhb + off);
                bh[nf*2][0] = r0; bh[nf*2][1] = r1;
                bh[nf*2+1][0] = r2; bh[nf*2+1][1] = r3;
                ldsm4(r0, r1, r2, r3, blb + off);
                bl[nf*2][0] = r0; bl[nf*2][1] = r1;
                bl[nf*2+1][0] = r2; bl[nf*2+1][1] = r3;
            }
            #pragma unroll
            for (int mi = 0; mi < 2; mi++)
                #pragma unroll
                for (int ni = 0; ni < 4; ni++) {
                    mma_bf16(acc[mi][ni], ah[mi], bh[ni]);
                    mma_bf16(acc[mi][ni], al[mi], bh[ni]);
                    mma_bf16(acc[mi][ni], ah[mi], bl[ni]);
                }
        }
        __syncthreads();
    }

    const int lc = lane & 3, lq = lane >> 2;
    #pragma unroll
    for (int ni = 0; ni < 4; ni++) {
        const int oc = nb*32 + wn*16 + ni*4 + lc;
        const float bL = bias[oc];
        const float bR = bias[oc + 256];
        #pragma unroll
        for (int mi = 0; mi < 2; mi++) {
            int mg = m0 + wm*32 + mi*16 + lq;
            {
                float zl = acc[mi][ni][0] + bL;
                float zr_ = acc[mi][ni][1] + bR;
                float sv = zl * (1.0f/(1.0f + expf(-zr_))) + g_x[(size_t)mg*HH + oc];
                g_s[(size_t)mg*HH + oc] = sv;
            }
            {
                int mg2 = mg + 8;
                float zl = acc[mi][ni][2] + bL;
                float zr_ = acc[mi][ni][3] + bR;
                float sv = zl * (1.0f/(1.0f + expf(-zr_))) + g_x[(size_t)mg2*HH + oc];
                g_s[(size_t)mg2*HH + oc] = sv;
            }
        }
    }
}

// ---------------------------------------------------------------------------
// ln_fused: LayerNorm + (mode&1) transpose-to-X + (mode&2) softplus heads.
//   block = 32 rows, 256 threads; grid GM/32.
// ---------------------------------------------------------------------------
__device__ __forceinline__ float softplus_f(float x) {
    return fmaxf(x, 0.f) + log1pf(expf(-fabsf(x)));
}

__global__ void __launch_bounds__(256) ln_fused_kernel(
    const float* __restrict__ lng, const float* __restrict__ lnb,
    const float* __restrict__ mu_w, const float* __restrict__ mu_b,
    const float* __restrict__ al_w, const float* __restrict__ al_b,
    float* __restrict__ out, int half, int mode)
{
    __shared__ float ys[32][260];
    const int wi = threadIdx.x >> 5, lane = threadIdx.x & 31;
    const int r0 = blockIdx.x*32;

    #pragma unroll
    for (int it = 0; it < 4; it++) {
        int rl = wi + it*8;
        size_t row = (size_t)(r0 + rl);
        const float4* sp = (const float4*)(g_s + row*HH);
        float4 v0 = sp[lane];
        float4 v1 = sp[lane + 32];

        float s1 = v0.x+v0.y+v0.z+v0.w + v1.x+v1.y+v1.z+v1.w;
        float s2 = v0.x*v0.x+v0.y*v0.y+v0.z*v0.z+v0.w*v0.w
                 + v1.x*v1.x+v1.y*v1.y+v1.z*v1.z+v1.w*v1.w;
        #pragma unroll
        for (int o = 16; o > 0; o >>= 1) {
            s1 += __shfl_xor_sync(0xffffffffu, s1, o);
            s2 += __shfl_xor_sync(0xffffffffu, s2, o);
        }
        float mean = s1 * (1.0f/HH);
        float var  = s2 * (1.0f/HH) - mean*mean;
        float inv  = rsqrtf(var + 1e-5f);

        const float4* gp = (const float4*)lng;
        const float4* bp = (const float4*)lnb;
        float4 g0 = gp[lane], g1 = gp[lane+32];
        float4 b0 = bp[lane], b1 = bp[lane+32];
        float4 y0, y1;
        y0.x = (v0.x-mean)*inv*g0.x + b0.x;  y0.y = (v0.y-mean)*inv*g0.y + b0.y;
        y0.z = (v0.z-mean)*inv*g0.z + b0.z;  y0.w = (v0.w-mean)*inv*g0.w + b0.w;
        y1.x = (v1.x-mean)*inv*g1.x + b1.x;  y1.y = (v1.y-mean)*inv*g1.y + b1.y;
        y1.z = (v1.z-mean)*inv*g1.z + b1.z;  y1.w = (v1.w-mean)*inv*g1.w + b1.w;

        float4* xp = (float4*)(g_x + row*HH);
        xp[lane] = y0;
        xp[lane + 32] = y1;
        *(float4*)&ys[rl][lane*4]       = y0;
        *(float4*)&ys[rl][128 + lane*4] = y1;

        if (mode & 2) {
            const float4* mp = (const float4*)mu_w;
            const float4* ap = (const float4*)al_w;
            float4 m0 = mp[lane], m1 = mp[lane+32];
            float4 a0 = ap[lane], a1 = ap[lane+32];
            float sm = y0.x*m0.x + y0.y*m0.y + y0.z*m0.z + y0.w*m0.w
                     + y1.x*m1.x + y1.y*m1.y + y1.z*m1.z + y1.w*m1.w;
            float sa = y0.x*a0.x + y0.y*a0.y + y0.z*a0.z + y0.w*a0.w
                     + y1.x*a1.x + y1.y*a1.y + y1.z*a1.z + y1.w*a1.w;
            #pragma unroll
            for (int o = 16; o > 0; o >>= 1) {
                sm += __shfl_xor_sync(0xffffffffu, sm, o);
                sa += __shfl_xor_sync(0xffffffffu, sa, o);
            }
            if (lane == 0) {
                out[row]        = softplus_f(sm + mu_b[0]);
                out[half + row] = softplus_f(sa + al_b[0]);
            }
        }
    }

    if (mode & 1) {
        __syncthreads();
        const int h = threadIdx.x;
        const int m = r0 >> 7, t0 = r0 & 127;
        union P4 { __nv_bfloat16 b[4]; ull u; };
        size_t dst = (size_t)h*((size_t)MM*256) + (size_t)m*256 + t0;
        #pragma unroll
        for (int j4 = 0; j4 < 8; j4++) {
            P4 ph, pl;
            #pragma unroll
            for (int i = 0; i < 4; i++) bsplit(ys[j4*4 + i][h], ph.b[i], pl.b[i]);
            *(ull*)(g_Xh + dst + j4*4) = ph.u;
            *(ull*)(g_Xl + dst + j4*4) = pl.u;
        }
    }
}

// ---------------------------------------------------------------------------
extern "C" void kernel_launch(void* const* d_in, const int* in_sizes, int n_in,
                              void* d_out, int out_size)
{
    const float* x      = (const float*)d_in[0];
    const float* enc_w  = (const float*)d_in[1];
    const float* enc_b  = (const float*)d_in[2];
    const float* log_dt = (const float*)d_in[3];
    const float* logA   = (const float*)d_in[4];
    const float* A_im   = (const float*)d_in[5];
    const float* C_re   = (const float*)d_in[6];
    const float* C_im   = (const float*)d_in[7];
    const float* Dp     = (const float*)d_in[8];
    const float* out_w  = (const float*)d_in[9];
    const float* out_b  = (const float*)d_in[10];
    const float* ln_g   = (const float*)d_in[11];
    const float* ln_b   = (const float*)d_in[12];
    const float* mu_w   = (const float*)d_in[13];
    const float* mu_b   = (const float*)d_in[14];
    const float* al_w   = (const float*)d_in[15];
    const float* al_b   = (const float*)d_in[16];
    float* out = (float*)d_out;

    enc_fused_kernel<<<GM/32, 256>>>(x, enc_w, enc_b);
    wconv_kernel<<<(NLAYERS*GN*GK)/256, 256>>>(out_w);
    genG_all_kernel<<<dim3(HH, NLAYERS), 128>>>(log_dt, logA, A_im, C_re, C_im, Dp);

    for (int l = 0; l < NLAYERS; l++) {
        const float* ldt = log_dt + l*HH;
        const float* lA  = logA   + (size_t)l*HH*NN;
        const float* Ai  = A_im   + (size_t)l*HH*NN;

        gemm_s4_kernel<<<dim3(4, HH), 256>>>(1, l);
        scanfix_kernel<<<(BB*HH*NN)/256, 256>>>(ldt, lA, Ai);
        gemm_s4_kernel<<<dim3(4, HH), 256>>>(2, l);
        backT_kernel<<<dim3(MM/32, TT/8, HH/32), 256>>>();
        gemm_glu_kernel<<<dim3(8, GM/128), 256>>>(l, out_b + (size_t)l*GN);
        ln_fused_kernel<<<GM/32, 256>>>(ln_g + l*HH, ln_b + l*HH,
                                        mu_w, mu_b, al_w, al_b,
                                        out, out_size/2,
                                        (l == NLAYERS-1) ? 2 : 1);
    }
}

// round 11
// speedup vs baseline: 1.0678x; 1.0678x over previous
#include <cuda_runtime.h>
#include <cuda_bf16.h>
#include <math.h>

// Problem constants
#define BB 16
#define LL 2048
#define DIN 8
#define HH 256
#define NN 64
#define NLAYERS 4
#define GM (BB*LL)      // 32768 rows
#define GK HH           // 256
#define GN (2*HH)       // 512
#define NC 16           // time chunks
#define TT (LL/NC)      // 128
#define MM (BB*NC)      // 256 chunk-columns

typedef unsigned long long ull;
typedef unsigned int u32;

// Scratch (device globals)
__device__ float g_x[(size_t)GM*HH];                       // activations (row,h)
__device__ float g_s[(size_t)GM*HH];                       // pre-LN (row,h)
__device__ __nv_bfloat16 g_gh[(size_t)GM*HH];              // gelu out hi (row,h)
__device__ __nv_bfloat16 g_gl[(size_t)GM*HH];              // gelu out lo
__device__ __nv_bfloat16 g_wh[(size_t)NLAYERS*GN*GK];      // GLU W hi
__device__ __nv_bfloat16 g_wl[(size_t)NLAYERS*GN*GK];      // GLU W lo
__device__ __nv_bfloat16 g_Xh[(size_t)HH*MM*256];          // X=[u;z0] hi (h,m,k)
__device__ __nv_bfloat16 g_Xl[(size_t)HH*MM*256];          // X lo
__device__ __nv_bfloat16 g_GAh[(size_t)NLAYERS*HH*128*256];// [K|V] hi (l,h,r,k)
__device__ __nv_bfloat16 g_GAl[(size_t)NLAYERS*HH*128*256];
__device__ __nv_bfloat16 g_GWh[(size_t)NLAYERS*HH*128*128];// W hi (l,h,i,s)
__device__ __nv_bfloat16 g_GWl[(size_t)NLAYERS*HH*128*128];
__device__ float g_zc[(size_t)HH*128*MM];                  // Zend0 (h,i,m)
__device__ float g_y[(size_t)HH*TT*MM];                    // conv out (h,t,m)

__device__ __forceinline__ void bsplit(float v, __nv_bfloat16& h, __nv_bfloat16& l) {
    h = __float2bfloat16_rn(v);
    l = __float2bfloat16_rn(v - __bfloat162float(h));
}

// ---------------------------------------------------------------------------
// Encoder (row,h) — R8 version
// ---------------------------------------------------------------------------
__global__ void enc_kernel(const float* __restrict__ x,
                           const float* __restrict__ w,
                           const float* __restrict__ b)
{
    int row = blockIdx.x;
    int h = threadIdx.x;
    __shared__ float xr[DIN];
    if (h < DIN) xr[h] = x[row*DIN + h];
    __syncthreads();
    float s = b[h];
    #pragma unroll
    for (int k = 0; k < DIN; k++)
        s = fmaf(xr[k], w[h*DIN + k], s);
    g_x[(size_t)row*HH + h] = s;
}

// ---------------------------------------------------------------------------
// One-shot GLU W -> bf16 hi/lo split
// ---------------------------------------------------------------------------
__global__ void wconv_kernel(const float* __restrict__ W)
{
    size_t i = (size_t)blockIdx.x*256 + threadIdx.x;
    float w = W[i];
    bsplit(w, g_wh[i], g_wl[i]);
}

// ---------------------------------------------------------------------------
__device__ __forceinline__ void s4_lambda(
    const float* log_dt, const float* logA_re, const float* A_im,
    int h, int n, float& Lr, float& Li, float& are, float& aim)
{
    float dt = expf(log_dt[h]);
    are = -expf(logA_re[h*NN + n]);
    aim = A_im[h*NN + n];
    float er = expf(dt*are);
    float dim = dt*aim;
    Lr = er*cosf(dim);
    Li = er*sinf(dim);
}

// ---------------------------------------------------------------------------
// fwdT (R8): g_x (row,h) fp32 -> X (h, m, t) bf16 hi/lo. Only needed for layer 0.
// ---------------------------------------------------------------------------
__global__ void __launch_bounds__(256) fwdT_kernel()
{
    const int m = blockIdx.x, h0 = blockIdx.y*32;
    const int b = m >> 4, c = m & 15;
    const size_t rbase = ((size_t)b*LL + c*TT)*HH;
    __shared__ float sT[128][33];
    const int tid = threadIdx.x;
    const int hl = (tid & 7)*4, tr0 = tid >> 3;
    #pragma unroll
    for (int p = 0; p < 4; p++) {
        int tt = p*32 + tr0;
        float4 v = *(const float4*)(g_x + rbase + (size_t)tt*HH + h0 + hl);
        sT[tt][hl] = v.x; sT[tt][hl+1] = v.y; sT[tt][hl+2] = v.z; sT[tt][hl+3] = v.w;
    }
    __syncthreads();
    const int w = tid >> 5, lane = tid & 31;
    union P4 { __nv_bfloat16 b[4]; ull u; };
    #pragma unroll
    for (int p = 0; p < 4; p++) {
        int hh = p*8 + w;
        int t0 = lane*4;
        P4 ph, pl;
        #pragma unroll
        for (int i = 0; i < 4; i++) bsplit(sT[t0+i][hh], ph.b[i], pl.b[i]);
        size_t dst = (size_t)(h0+hh)*((size_t)MM*256) + (size_t)m*256 + t0;
        *(ull*)(g_Xh + dst) = ph.u;
        *(ull*)(g_Xl + dst) = pl.u;
    }
}

// ---------------------------------------------------------------------------
// genG_all: per-(layer,channel) G_A=[K|V] (128x256), G_W (128x128), bf16 hi/lo.
// ---------------------------------------------------------------------------
__global__ void __launch_bounds__(128) genG_all_kernel(
    const float* __restrict__ log_dt_a,
    const float* __restrict__ logA_a,
    const float* __restrict__ A_im_a,
    const float* __restrict__ C_re_a,
    const float* __restrict__ C_im_a,
    const float* __restrict__ Dp_a)
{
    const int h = blockIdx.x;
    const int l = blockIdx.y;
    const int t = threadIdx.x;
    const float* log_dt = log_dt_a + l*HH;
    const float* logA_re = logA_a + (size_t)l*HH*NN;
    const float* A_im = A_im_a + (size_t)l*HH*NN;
    const float* C_re = C_re_a + (size_t)l*HH*NN;
    const float* C_im = C_im_a + (size_t)l*HH*NN;

    __shared__ float s_cr[64], s_ci[64], s_lr[64], s_li[64];
    __shared__ float s_pr[64][33], s_pi[64][33];
    __shared__ float s_k[128];

    float pr = 1.f, pi = 0.f;
    if (t < 64) {
        float are, aim, Lr, Li;
        s4_lambda(log_dt, logA_re, A_im, h, t, Lr, Li, are, aim);
        s_lr[t] = Lr; s_li[t] = Li;
        float Cre = C_re[h*NN + t], Cim = C_im[h*NN + t];
        float nr = Lr - 1.f, ni = Li;
        float tr = Cre*nr - Cim*ni, ti = Cre*ni + Cim*nr;
        float inv = 2.f/(are*are + aim*aim);
        s_cr[t] =  inv*(tr*are + ti*aim);
        s_ci[t] = -inv*(ti*are - tr*aim);
    }
    __syncthreads();
    const float Dh = Dp_a[l*HH + h];
    __nv_bfloat16* GAh = g_GAh + ((size_t)l*HH + h)*128*256;
    __nv_bfloat16* GAl = g_GAl + ((size_t)l*HH + h)*128*256;
    __nv_bfloat16* GWh = g_GWh + ((size_t)l*HH + h)*128*128;
    __nv_bfloat16* GWl = g_GWl + ((size_t)l*HH + h)*128*128;

    for (int cd = 0; cd < 4; cd++) {
        if (t < 64) {
            float Lr = s_lr[t], Li = s_li[t];
            #pragma unroll
            for (int dd = 0; dd < 32; dd++) {
                s_pr[t][dd] = pr; s_pi[t][dd] = pi;
                float npr = pr*Lr - pi*Li;
                float npi = pr*Li + pi*Lr;
                pr = npr; pi = npi;
            }
        }
        __syncthreads();
        {
            int dd = t >> 2, q = t & 3;
            float part = 0.f;
            for (int n = q*16; n < q*16 + 16; n++)
                part += s_cr[n]*s_pr[n][dd] + s_ci[n]*s_pi[n][dd];
            part += __shfl_xor_sync(0xffffffffu, part, 1);
            part += __shfl_xor_sync(0xffffffffu, part, 2);
            int d = cd*32 + dd;
            if (q == 0) s_k[d] = part + (d == 0 ? Dh : 0.f);
        }
        for (int dd = 0; dd < 32; dd++) {
            int d = cd*32 + dd, r = d - 1;
            if (r >= 0) {
                float v;
                if (t < 64)
                    v = s_cr[t]*s_pr[t][dd] + s_ci[t]*s_pi[t][dd];
                else {
                    int j = t - 64;
                    v = s_ci[j]*s_pr[j][dd] - s_cr[j]*s_pi[j][dd];
                }
                __nv_bfloat16 hb, lb; bsplit(v, hb, lb);
                GAh[r*256 + 128 + t] = hb;
                GAl[r*256 + 128 + t] = lb;
            }
        }
        for (int p = 0; p < 32; p++) {
            int row = p*4 + (t >> 5);
            int sc = t & 31;
            int s = 96 - cd*32 + sc;
            int dd = 31 - sc;
            float v = (row < 64) ? s_pr[row][dd] : s_pi[row-64][dd];
            __nv_bfloat16 hb, lb; bsplit(v, hb, lb);
            GWh[row*128 + s] = hb;
            GWl[row*128 + s] = lb;
        }
        __syncthreads();
    }
    if (t < 64) { s_pr[t][0] = pr; s_pi[t][0] = pi; }
    __syncthreads();
    {
        float v;
        if (t < 64)
            v = s_cr[t]*s_pr[t][0] + s_ci[t]*s_pi[t][0];
        else {
            int j = t - 64;
            v = s_ci[j]*s_pr[j][0] - s_cr[j]*s_pi[j][0];
        }
        __nv_bfloat16 hb, lb; bsplit(v, hb, lb);
        GAh[127*256 + 128 + t] = hb;
        GAl[127*256 + 128 + t] = lb;
    }
    for (int r = 0; r < 128; r++) {
        float v = (t <= r) ? s_k[r - t] : 0.f;
        __nv_bfloat16 hb, lb; bsplit(v, hb, lb);
        GAh[r*256 + t] = hb;
        GAl[r*256 + t] = lb;
    }
}

// ---------------------------------------------------------------------------
// scanfix: compose Zend0 across chunks; write z0 (bf16 hi/lo) into X rows 128+
// ---------------------------------------------------------------------------
__global__ void __launch_bounds__(256) scanfix_kernel(
    const float* __restrict__ log_dt,
    const float* __restrict__ logA_re,
    const float* __restrict__ A_im)
{
    int gid = blockIdx.x*256 + threadIdx.x;
    int n = gid & 63, h = (gid >> 6) & 255, b = gid >> 14;

    float Lr, Li, are, aim;
    s4_lambda(log_dt, logA_re, A_im, h, n, Lr, Li, are, aim);
    #pragma unroll
    for (int s = 0; s < 7; s++) {
        float nr = Lr*Lr - Li*Li, ni = 2.f*Lr*Li;
        Lr = nr; Li = ni;
    }

    const float* zcre = g_zc + (size_t)h*128*MM + n*MM;
    const float* zcim = zcre + 64*MM;
    __nv_bfloat16* Xh = g_Xh + (size_t)h*MM*256;
    __nv_bfloat16* Xl = g_Xl + (size_t)h*MM*256;

    float cr = 0.f, ci = 0.f;
    #pragma unroll
    for (int c = 0; c < NC; c++) {
        int m = b*16 + c;
        __nv_bfloat16 hb, lb;
        bsplit(cr, hb, lb);
        Xh[(size_t)m*256 + 128 + n] = hb; Xl[(size_t)m*256 + 128 + n] = lb;
        bsplit(ci, hb, lb);
        Xh[(size_t)m*256 + 192 + n] = hb; Xl[(size_t)m*256 + 192 + n] = lb;
        float zr = zcre[m], zi = zcim[m];
        float nr = Lr*cr - Li*ci + zr;
        float ni = Lr*ci + Li*cr + zi;
        cr = nr; ci = ni;
    }
}

// ---------------------------------------------------------------------------
// GEMM building blocks (mma.sync path — sm_100 plain target)
// ---------------------------------------------------------------------------
__device__ __forceinline__ void cp16(u32 dst, const void* src) {
    asm volatile("cp.async.cg.shared.global [%0], [%1], 16;" :: "r"(dst), "l"(src));
}
__device__ __forceinline__ void ldsm4(u32& r0, u32& r1, u32& r2, u32& r3, u32 addr) {
    asm volatile("ldmatrix.sync.aligned.m8n8.x4.shared.b16 {%0,%1,%2,%3},[%4];"
                 : "=r"(r0), "=r"(r1), "=r"(r2), "=r"(r3) : "r"(addr));
}
__device__ __forceinline__ void mma_bf16(float* d, const u32* a, const u32* b) {
    asm volatile(
        "mma.sync.aligned.m16n8k16.row.col.f32.bf16.bf16.f32 "
        "{%0,%1,%2,%3},{%4,%5,%6,%7},{%8,%9},{%0,%1,%2,%3};"
        : "+f"(d[0]), "+f"(d[1]), "+f"(d[2]), "+f"(d[3])
        : "r"(a[0]), "r"(a[1]), "r"(a[2]), "r"(a[3]), "r"(b[0]), "r"(b[1]));
}

#define STG2 24576

// ---------------------------------------------------------------------------
// gemm_s4: per-channel bf16x3 (pass1: Zend0 = G_W*U, K=128; pass2: Y = G_A*X, K=256)
// ---------------------------------------------------------------------------
__global__ void __launch_bounds__(256) gemm_s4_kernel(int pass, int l)
{
    __shared__ __align__(128) char smem_buf[2*STG2];
    const int h  = blockIdx.y;
    const int mt = blockIdx.x;
    const int tid = threadIdx.x, lane = tid & 31, w = tid >> 5;
    const int wm = w & 3, wn = w >> 2;

    const int NK = (pass == 1) ? 128 : 256;
    const __nv_bfloat16* Ahp = (pass == 1) ? g_GWh + ((size_t)l*HH + h)*128*128
                                           : g_GAh + ((size_t)l*HH + h)*128*256;
    const __nv_bfloat16* Alp = (pass == 1) ? g_GWl + ((size_t)l*HH + h)*128*128
                                           : g_GAl + ((size_t)l*HH + h)*128*256;
    const __nv_bfloat16* Bhp = g_Xh + (size_t)h*MM*256;
    const __nv_bfloat16* Blp = g_Xl + (size_t)h*MM*256;
    float* outp = ((pass == 1) ? g_zc : g_y) + (size_t)h*128*MM;

    const int nch = NK/32;
    const u32 smem_base = (u32)__cvta_generic_to_shared(smem_buf);

    float acc[2][4][4];
    #pragma unroll
    for (int mi = 0; mi < 2; mi++)
        #pragma unroll
        for (int ni = 0; ni < 4; ni++)
            #pragma unroll
            for (int r = 0; r < 4; r++) acc[mi][ni][r] = 0.f;

    auto load_chunk = [&](int kc, int stage) {
        int k0 = kc*32;
        u32 base = smem_base + stage*STG2;
        #pragma unroll
        for (int i = 0; i < 2; i++) {
            int gid = i*256 + tid;
            int row = gid >> 2, g = gid & 3;
            int pg = g ^ ((row >> 1) & 3);
            cp16(base + row*64 + pg*16,        Ahp + (size_t)row*NK + k0 + g*8);
            cp16(base + 8192 + row*64 + pg*16, Alp + (size_t)row*NK + k0 + g*8);
        }
        {
            int row = tid >> 2, g = tid & 3;
            int pg = g ^ ((row >> 1) & 3);
            cp16(base + 16384 + row*64 + pg*16, Bhp + (size_t)(mt*64 + row)*256 + k0 + g*8);
            cp16(base + 20480 + row*64 + pg*16, Blp + (size_t)(mt*64 + row)*256 + k0 + g*8);
        }
    };

    load_chunk(0, 0);
    asm volatile("cp.async.commit_group;");

    for (int kc = 0; kc < nch; kc++) {
        if (kc + 1 < nch) load_chunk(kc + 1, (kc + 1) & 1);
        asm volatile("cp.async.commit_group;");
        asm volatile("cp.async.wait_group 1;");
        __syncthreads();

        const u32 ab  = smem_base + (kc & 1)*STG2;
        const u32 alb = ab + 8192, bhb = ab + 16384, blb = ab + 20480;

        #pragma unroll
        for (int ks = 0; ks < 2; ks++) {
            const int grp = lane >> 3, rh = lane & 7;
            u32 ah[2][4], al[2][4];
            #pragma unroll
            for (int mi = 0; mi < 2; mi++) {
                int row = wm*32 + mi*16 + rh + (grp & 1)*8;
                int kg  = 2*ks + (grp >> 1);
                u32 off = row*64 + ((kg ^ ((row >> 1) & 3))*16);
                ldsm4(ah[mi][0], ah[mi][1], ah[mi][2], ah[mi][3], ab + off);
                ldsm4(al[mi][0], al[mi][1], al[mi][2], al[mi][3], alb + off);
            }
            u32 bh[4][2], bl[4][2];
            #pragma unroll
            for (int nf = 0; nf < 2; nf++) {
                int row = wn*32 + nf*16 + rh + (grp >> 1)*8;
                int kg  = 2*ks + (grp & 1);
                u32 off = row*64 + ((kg ^ ((row >> 1) & 3))*16);
                u32 r0, r1, r2, r3;
                ldsm4(r0, r1, r2, r3, bhb + off);
                bh[nf*2][0] = r0; bh[nf*2][1] = r1;
                bh[nf*2+1][0] = r2; bh[nf*2+1][1] = r3;
                ldsm4(r0, r1, r2, r3, blb + off);
                bl[nf*2][0] = r0; bl[nf*2][1] = r1;
                bl[nf*2+1][0] = r2; bl[nf*2+1][1] = r3;
            }
            #pragma unroll
            for (int mi = 0; mi < 2; mi++)
                #pragma unroll
                for (int ni = 0; ni < 4; ni++) {
                    mma_bf16(acc[mi][ni], ah[mi], bh[ni]);
                    mma_bf16(acc[mi][ni], al[mi], bh[ni]);
                    mma_bf16(acc[mi][ni], ah[mi], bl[ni]);
                }
        }
        __syncthreads();
    }

    const int lq = lane >> 2, lc = lane & 3;
    #pragma unroll
    for (int mi = 0; mi < 2; mi++) {
        #pragma unroll
        for (int ni = 0; ni < 4; ni++) {
            int row = wm*32 + mi*16 + lq;
            int col = mt*64 + wn*32 + ni*8 + lc*2;
            float2 v0; v0.x = acc[mi][ni][0]; v0.y = acc[mi][ni][1];
            float2 v1; v1.x = acc[mi][ni][2]; v1.y = acc[mi][ni][3];
            *(float2*)(outp + (size_t)row*MM + col) = v0;
            *(float2*)(outp + (size_t)(row+8)*MM + col) = v1;
        }
    }
}

// ---------------------------------------------------------------------------
// backT: g_y (h,t,m) fp32 -> gelu -> g_gh/g_gl (row,h) bf16 hi/lo
// ---------------------------------------------------------------------------
__global__ void __launch_bounds__(256) backT_kernel()
{
    const int m0 = blockIdx.x*32, t0 = blockIdx.y*8, h0 = blockIdx.z*32;
    __shared__ float sB[256][33];
    const int tid = threadIdx.x, w = tid >> 5, lane = tid & 31;

    for (int i = 0; i < 32; i++) {
        int seg = w*32 + i;
        int hh = seg >> 3, tt = seg & 7;
        float v = g_y[(size_t)(h0+hh)*TT*MM + (size_t)(t0+tt)*MM + m0 + lane];
        sB[tt*32 + lane][hh] = v;
    }
    __syncthreads();
    for (int i = 0; i < 32; i++) {
        int pair = w*32 + i;
        int mm = pair >> 3, tt = pair & 7;
        int m = m0 + mm;
        int b = m >> 4, cc = m & 15;
        size_t row = (size_t)b*LL + cc*TT + t0 + tt;
        float yv = sB[tt*32 + mm][lane];
        float gv = 0.5f*yv*(1.0f + erff(yv*0.70710678118654752f));
        __nv_bfloat16 hb, lb; bsplit(gv, hb, lb);
        g_gh[row*HH + h0 + lane] = hb;
        g_gl[row*HH + h0 + lane] = lb;
    }
}

// ---------------------------------------------------------------------------
// GLU GEMM (R8-proven): bf16x3, 128m x 64 gemm-cols, static 48KB smem,
// fused GLU+bias+residual. 8 warps = 4m x 2n; warp tile 32m x 32n.
// ---------------------------------------------------------------------------
__global__ void __launch_bounds__(256) gemm_glu_kernel(int l, const float* __restrict__ bias)
{
    __shared__ __align__(128) char smem_buf[2*STG2];

    const int m0  = blockIdx.y * 128;
    const int nb  = blockIdx.x;
    const int tid = threadIdx.x;
    const int lane = tid & 31, w = tid >> 5;
    const int wm = w & 3;
    const int wn = w >> 2;

    const __nv_bfloat16* Whp = g_wh + (size_t)l*GN*GK;
    const __nv_bfloat16* Wlp = g_wl + (size_t)l*GN*GK;

    const u32 smem_base = (u32)__cvta_generic_to_shared(smem_buf);

    float acc[2][4][4];
    #pragma unroll
    for (int mi = 0; mi < 2; mi++)
        #pragma unroll
        for (int ni = 0; ni < 4; ni++)
            #pragma unroll
            for (int r = 0; r < 4; r++) acc[mi][ni][r] = 0.f;

    auto load_chunk = [&](int kc, int stage) {
        int k0 = kc*32;
        u32 base = smem_base + stage*STG2;
        #pragma unroll
        for (int i = 0; i < 2; i++) {
            int gid = i*256 + tid;
            int row = gid >> 2, g = gid & 3;
            int pg = g ^ ((row >> 1) & 3);
            cp16(base + row*64 + pg*16,        g_gh + (size_t)(m0 + row)*GK + k0 + g*8);
            cp16(base + 8192 + row*64 + pg*16, g_gl + (size_t)(m0 + row)*GK + k0 + g*8);
        }
        {
            int row = tid >> 2, g = tid & 3;
            int pg = g ^ ((row >> 1) & 3);
            int wr = nb*32 + (row >> 1) + (row & 1)*256;
            cp16(base + 16384 + row*64 + pg*16, Whp + (size_t)wr*GK + k0 + g*8);
            cp16(base + 20480 + row*64 + pg*16, Wlp + (size_t)wr*GK + k0 + g*8);
        }
    };

    load_chunk(0, 0);
    asm volatile("cp.async.commit_group;");

    #pragma unroll 1
    for (int kc = 0; kc < 8; kc++) {
        if (kc + 1 < 8) load_chunk(kc + 1, (kc + 1) & 1);
        asm volatile("cp.async.commit_group;");
        asm volatile("cp.async.wait_group 1;");
        __syncthreads();

        const u32 ab  = smem_base + (kc & 1)*STG2;
        const u32 alb = ab + 8192, bhb = ab + 16384, blb = ab + 20480;

        #pragma unroll
        for (int ks = 0; ks < 2; ks++) {
            const int grp = lane >> 3, rh = lane & 7;
            u32 ah[2][4], al[2][4];
            #pragma unroll
            for (int mi = 0; mi < 2; mi++) {
                int row = wm*32 + mi*16 + rh + (grp & 1)*8;
                int kg  = 2*ks + (grp >> 1);
                u32 off = row*64 + ((kg ^ ((row >> 1) & 3))*16);
                ldsm4(ah[mi][0], ah[mi][1], ah[mi][2], ah[mi][3], ab + off);
                ldsm4(al[mi][0], al[mi][1], al[mi][2], al[mi][3], alb + off);
            }
            u32 bh[4][2], bl[4][2];
            #pragma unroll
            for (int nf = 0; nf < 2; nf++) {
                int row = wn*32 + nf*16 + rh + (grp >> 1)*8;
                int kg  = 2*ks + (grp & 1);
                u32 off = row*64 + ((kg ^ ((row >> 1) & 3))*16);
                u32 r0, r1, r2, r3;
                ldsm4(r0, r1, r2, r3, bhb + off);
                bh[nf*2][0] = r0; bh[nf*2][1] = r1;
                bh[nf*2+1][0] = r2; bh[nf*2+1][1] = r3;
                ldsm4(r0, r1, r2, r3, blb + off);
                bl[nf*2][0] = r0; bl[nf*2][1] = r1;
                bl[nf*2+1][0] = r2; bl[nf*2+1][1] = r3;
            }
            #pragma unroll
            for (int mi = 0; mi < 2; mi++)
                #pragma unroll
                for (int ni = 0; ni < 4; ni++) {
                    mma_bf16(acc[mi][ni], ah[mi], bh[ni]);
                    mma_bf16(acc[mi][ni], al[mi], bh[ni]);
                    mma_bf16(acc[mi][ni], ah[mi], bl[ni]);
                }
        }
        __syncthreads();
    }

    const int lc = lane & 3, lq = lane >> 2;
    #pragma unroll
    for (int ni = 0; ni < 4; ni++) {
        const int oc = nb*32 + wn*16 + ni*4 + lc;
        const float bL = bias[oc];
        const float bR = bias[oc + 256];
        #pragma unroll
        for (int mi = 0; mi < 2; mi++) {
            int mg = m0 + wm*32 + mi*16 + lq;
            {
                float zl = acc[mi][ni][0] + bL;
                float zr_ = acc[mi][ni][1] + bR;
                float sv = zl * (1.0f/(1.0f + expf(-zr_))) + g_x[(size_t)mg*HH + oc];
                g_s[(size_t)mg*HH + oc] = sv;
            }
            {
                int mg2 = mg + 8;
                float zl = acc[mi][ni][2] + bL;
                float zr_ = acc[mi][ni][3] + bR;
                float sv = zl * (1.0f/(1.0f + expf(-zr_))) + g_x[(size_t)mg2*HH + oc];
                g_s[(size_t)mg2*HH + oc] = sv;
            }
        }
    }
}

// ---------------------------------------------------------------------------
// ln_fused v2: LayerNorm + (mode&1) COALESCED transpose-to-X + (mode&2) heads.
//   block = 32 rows, 256 threads; grid GM/32. smem ysT[h][t] for the transpose.
//   Transposed writes: warp w, lane-group (lane>>3) -> one h; 8 lanes x 8B
//   contiguous = 64B segments (vs the scattered 8B stores that sank R9/R10).
// ---------------------------------------------------------------------------
__device__ __forceinline__ float softplus_f(float x) {
    return fmaxf(x, 0.f) + log1pf(expf(-fabsf(x)));
}

__global__ void __launch_bounds__(256) ln_fused_kernel(
    const float* __restrict__ lng, const float* __restrict__ lnb,
    const float* __restrict__ mu_w, const float* __restrict__ mu_b,
    const float* __restrict__ al_w, const float* __restrict__ al_b,
    float* __restrict__ out, int half, int mode)
{
    __shared__ float ysT[256][33];     // [h][t]
    const int wi = threadIdx.x >> 5, lane = threadIdx.x & 31;
    const int r0 = blockIdx.x*32;

    #pragma unroll
    for (int it = 0; it < 4; it++) {
        int rl = wi + it*8;
        size_t row = (size_t)(r0 + rl);
        const float4* sp = (const float4*)(g_s + row*HH);
        float4 v0 = sp[lane];
        float4 v1 = sp[lane + 32];

        float s1 = v0.x+v0.y+v0.z+v0.w + v1.x+v1.y+v1.z+v1.w;
        float s2 = v0.x*v0.x+v0.y*v0.y+v0.z*v0.z+v0.w*v0.w
                 + v1.x*v1.x+v1.y*v1.y+v1.z*v1.z+v1.w*v1.w;
        #pragma unroll
        for (int o = 16; o > 0; o >>= 1) {
            s1 += __shfl_xor_sync(0xffffffffu, s1, o);
            s2 += __shfl_xor_sync(0xffffffffu, s2, o);
        }
        float mean = s1 * (1.0f/HH);
        float var  = s2 * (1.0f/HH) - mean*mean;
        float inv  = rsqrtf(var + 1e-5f);

        const float4* gp = (const float4*)lng;
        const float4* bp = (const float4*)lnb;
        float4 g0 = gp[lane], g1 = gp[lane+32];
        float4 b0 = bp[lane], b1 = bp[lane+32];
        float4 y0, y1;
        y0.x = (v0.x-mean)*inv*g0.x + b0.x;  y0.y = (v0.y-mean)*inv*g0.y + b0.y;
        y0.z = (v0.z-mean)*inv*g0.z + b0.z;  y0.w = (v0.w-mean)*inv*g0.w + b0.w;
        y1.x = (v1.x-mean)*inv*g1.x + b1.x;  y1.y = (v1.y-mean)*inv*g1.y + b1.y;
        y1.z = (v1.z-mean)*inv*g1.z + b1.z;  y1.w = (v1.w-mean)*inv*g1.w + b1.w;

        float4* xp = (float4*)(g_x + row*HH);
        xp[lane] = y0;
        xp[lane + 32] = y1;

        if (mode & 1) {
            int hb0 = lane*4;
            ysT[hb0+0][rl] = y0.x; ysT[hb0+1][rl] = y0.y;
            ysT[hb0+2][rl] = y0.z; ysT[hb0+3][rl] = y0.w;
            ysT[128+hb0+0][rl] = y1.x; ysT[128+hb0+1][rl] = y1.y;
            ysT[128+hb0+2][rl] = y1.z; ysT[128+hb0+3][rl] = y1.w;
        }

        if (mode & 2) {
            const float4* mp = (const float4*)mu_w;
            const float4* ap = (const float4*)al_w;
            float4 m0 = mp[lane], m1 = mp[lane+32];
            float4 a0 = ap[lane], a1 = ap[lane+32];
            float sm = y0.x*m0.x + y0.y*m0.y + y0.z*m0.z + y0.w*m0.w
                     + y1.x*m1.x + y1.y*m1.y + y1.z*m1.z + y1.w*m1.w;
            float sa = y0.x*a0.x + y0.y*a0.y + y0.z*a0.z + y0.w*a0.w
                     + y1.x*a1.x + y1.y*a1.y + y1.z*a1.z + y1.w*a1.w;
            #pragma unroll
            for (int o = 16; o > 0; o >>= 1) {
                sm += __shfl_xor_sync(0xffffffffu, sm, o);
                sa += __shfl_xor_sync(0xffffffffu, sa, o);
            }
            if (lane == 0) {
                out[row]        = softplus_f(sm + mu_b[0]);
                out[half + row] = softplus_f(sa + al_b[0]);
            }
        }
    }

    if (mode & 1) {
        __syncthreads();
        const int m = r0 >> 7, tb = r0 & 127;
        union P4 { __nv_bfloat16 b[4]; ull u; };
        #pragma unroll
        for (int p = 0; p < 8; p++) {
            int h  = p*32 + wi*4 + (lane >> 3);
            int tq = lane & 7;
            P4 ph, pl;
            #pragma unroll
            for (int i = 0; i < 4; i++) bsplit(ysT[h][tq*4 + i], ph.b[i], pl.b[i]);
            size_t dst = (size_t)h*((size_t)MM*256) + (size_t)m*256 + tb + tq*4;
            *(ull*)(g_Xh + dst) = ph.u;
            *(ull*)(g_Xl + dst) = pl.u;
        }
    }
}

// ---------------------------------------------------------------------------
extern "C" void kernel_launch(void* const* d_in, const int* in_sizes, int n_in,
                              void* d_out, int out_size)
{
    const float* x      = (const float*)d_in[0];
    const float* enc_w  = (const float*)d_in[1];
    const float* enc_b  = (const float*)d_in[2];
    const float* log_dt = (const float*)d_in[3];
    const float* logA   = (const float*)d_in[4];
    const float* A_im   = (const float*)d_in[5];
    const float* C_re   = (const float*)d_in[6];
    const float* C_im   = (const float*)d_in[7];
    const float* Dp     = (const float*)d_in[8];
    const float* out_w  = (const float*)d_in[9];
    const float* out_b  = (const float*)d_in[10];
    const float* ln_g   = (const float*)d_in[11];
    const float* ln_b   = (const float*)d_in[12];
    const float* mu_w   = (const float*)d_in[13];
    const float* mu_b   = (const float*)d_in[14];
    const float* al_w   = (const float*)d_in[15];
    const float* al_b   = (const float*)d_in[16];
    float* out = (float*)d_out;

    enc_kernel<<<GM, HH>>>(x, enc_w, enc_b);
    wconv_kernel<<<(NLAYERS*GN*GK)/256, 256>>>(out_w);
    genG_all_kernel<<<dim3(HH, NLAYERS), 128>>>(log_dt, logA, A_im, C_re, C_im, Dp);
    fwdT_kernel<<<dim3(MM, 8), 256>>>();     // X for layer 0 only

    for (int l = 0; l < NLAYERS; l++) {
        const float* ldt = log_dt + l*HH;
        const float* lA  = logA   + (size_t)l*HH*NN;
        const float* Ai  = A_im   + (size_t)l*HH*NN;

        gemm_s4_kernel<<<dim3(4, HH), 256>>>(1, l);
        scanfix_kernel<<<(BB*HH*NN)/256, 256>>>(ldt, lA, Ai);
        gemm_s4_kernel<<<dim3(4, HH), 256>>>(2, l);
        backT_kernel<<<dim3(MM/32, TT/8, HH/32), 256>>>();
        gemm_glu_kernel<<<dim3(8, GM/128), 256>>>(l, out_b + (size_t)l*GN);
        ln_fused_kernel<<<GM/32, 256>>>(ln_g + l*HH, ln_b + l*HH,
                                        mu_w, mu_b, al_w, al_b,
                                        out, out_size/2,
                                        (l == NLAYERS-1) ? 2 : 1);
    }
}

// round 13
// speedup vs baseline: 1.1182x; 1.0472x over previous
#include <cuda_runtime.h>
#include <cuda_bf16.h>
#include <math.h>

// Problem constants
#define BB 16
#define LL 2048
#define DIN 8
#define HH 256
#define NN 64
#define NLAYERS 4
#define GM (BB*LL)      // 32768 rows
#define GK HH           // 256
#define GN (2*HH)       // 512
#define NC 16           // time chunks
#define TT (LL/NC)      // 128
#define MM (BB*NC)      // 256 chunk-columns

typedef unsigned long long ull;
typedef unsigned int u32;

// Scratch (device globals)
__device__ float g_x[(size_t)GM*HH];                       // activations (row,h)
__device__ float g_s[(size_t)GM*HH];                       // pre-LN (row,h)
__device__ __nv_bfloat16 g_gh[(size_t)GM*HH];              // gelu out hi, (h,m,t) layout
__device__ __nv_bfloat16 g_gl[(size_t)GM*HH];              // gelu out lo, (h,m,t) layout
__device__ __nv_bfloat16 g_wh[(size_t)NLAYERS*GN*GK];      // GLU W hi
__device__ __nv_bfloat16 g_wl[(size_t)NLAYERS*GN*GK];      // GLU W lo
__device__ __nv_bfloat16 g_Xh[(size_t)HH*MM*256];          // X=[u;z0] hi (h,m,k)
__device__ __nv_bfloat16 g_Xl[(size_t)HH*MM*256];          // X lo
__device__ __nv_bfloat16 g_GAh[(size_t)NLAYERS*HH*128*256];// [K|V] hi (l,h,r,k)
__device__ __nv_bfloat16 g_GAl[(size_t)NLAYERS*HH*128*256];
__device__ __nv_bfloat16 g_GWh[(size_t)NLAYERS*HH*128*128];// W hi (l,h,i,s)
__device__ __nv_bfloat16 g_GWl[(size_t)NLAYERS*HH*128*128];
__device__ float g_zc[(size_t)HH*128*MM];                  // Zend0 (h,i,m)

__device__ __forceinline__ void bsplit(float v, __nv_bfloat16& h, __nv_bfloat16& l) {
    h = __float2bfloat16_rn(v);
    l = __float2bfloat16_rn(v - __bfloat162float(h));
}

// ---------------------------------------------------------------------------
// Encoder (row,h)
// ---------------------------------------------------------------------------
__global__ void enc_kernel(const float* __restrict__ x,
                           const float* __restrict__ w,
                           const float* __restrict__ b)
{
    int row = blockIdx.x;
    int h = threadIdx.x;
    __shared__ float xr[DIN];
    if (h < DIN) xr[h] = x[row*DIN + h];
    __syncthreads();
    float s = b[h];
    #pragma unroll
    for (int k = 0; k < DIN; k++)
        s = fmaf(xr[k], w[h*DIN + k], s);
    g_x[(size_t)row*HH + h] = s;
}

// ---------------------------------------------------------------------------
// One-shot GLU W -> bf16 hi/lo split
// ---------------------------------------------------------------------------
__global__ void wconv_kernel(const float* __restrict__ W)
{
    size_t i = (size_t)blockIdx.x*256 + threadIdx.x;
    float w = W[i];
    bsplit(w, g_wh[i], g_wl[i]);
}

// ---------------------------------------------------------------------------
__device__ __forceinline__ void s4_lambda(
    const float* log_dt, const float* logA_re, const float* A_im,
    int h, int n, float& Lr, float& Li, float& are, float& aim)
{
    float dt = expf(log_dt[h]);
    are = -expf(logA_re[h*NN + n]);
    aim = A_im[h*NN + n];
    float er = expf(dt*are);
    float dim = dt*aim;
    Lr = er*cosf(dim);
    Li = er*sinf(dim);
}

// ---------------------------------------------------------------------------
// fwdT: g_x (row,h) fp32 -> X (h, m, t) bf16 hi/lo. Layer-0 only.
// ---------------------------------------------------------------------------
__global__ void __launch_bounds__(256) fwdT_kernel()
{
    const int m = blockIdx.x, h0 = blockIdx.y*32;
    const int b = m >> 4, c = m & 15;
    const size_t rbase = ((size_t)b*LL + c*TT)*HH;
    __shared__ float sT[128][33];
    const int tid = threadIdx.x;
    const int hl = (tid & 7)*4, tr0 = tid >> 3;
    #pragma unroll
    for (int p = 0; p < 4; p++) {
        int tt = p*32 + tr0;
        float4 v = *(const float4*)(g_x + rbase + (size_t)tt*HH + h0 + hl);
        sT[tt][hl] = v.x; sT[tt][hl+1] = v.y; sT[tt][hl+2] = v.z; sT[tt][hl+3] = v.w;
    }
    __syncthreads();
    const int w = tid >> 5, lane = tid & 31;
    union P4 { __nv_bfloat16 b[4]; ull u; };
    #pragma unroll
    for (int p = 0; p < 4; p++) {
        int hh = p*8 + w;
        int t0 = lane*4;
        P4 ph, pl;
        #pragma unroll
        for (int i = 0; i < 4; i++) bsplit(sT[t0+i][hh], ph.b[i], pl.b[i]);
        size_t dst = (size_t)(h0+hh)*((size_t)MM*256) + (size_t)m*256 + t0;
        *(ull*)(g_Xh + dst) = ph.u;
        *(ull*)(g_Xl + dst) = pl.u;
    }
}

// ---------------------------------------------------------------------------
// genG_all: per-(layer,channel) G_A=[K|V] (128x256), G_W (128x128), bf16 hi/lo.
// ---------------------------------------------------------------------------
__global__ void __launch_bounds__(128) genG_all_kernel(
    const float* __restrict__ log_dt_a,
    const float* __restrict__ logA_a,
    const float* __restrict__ A_im_a,
    const float* __restrict__ C_re_a,
    const float* __restrict__ C_im_a,
    const float* __restrict__ Dp_a)
{
    const int h = blockIdx.x;
    const int l = blockIdx.y;
    const int t = threadIdx.x;
    const float* log_dt = log_dt_a + l*HH;
    const float* logA_re = logA_a + (size_t)l*HH*NN;
    const float* A_im = A_im_a + (size_t)l*HH*NN;
    const float* C_re = C_re_a + (size_t)l*HH*NN;
    const float* C_im = C_im_a + (size_t)l*HH*NN;

    __shared__ float s_cr[64], s_ci[64], s_lr[64], s_li[64];
    __shared__ float s_pr[64][33], s_pi[64][33];
    __shared__ float s_k[128];

    float pr = 1.f, pi = 0.f;
    if (t < 64) {
        float are, aim, Lr, Li;
        s4_lambda(log_dt, logA_re, A_im, h, t, Lr, Li, are, aim);
        s_lr[t] = Lr; s_li[t] = Li;
        float Cre = C_re[h*NN + t], Cim = C_im[h*NN + t];
        float nr = Lr - 1.f, ni = Li;
        float tr = Cre*nr - Cim*ni, ti = Cre*ni + Cim*nr;
        float inv = 2.f/(are*are + aim*aim);
        s_cr[t] =  inv*(tr*are + ti*aim);
        s_ci[t] = -inv*(ti*are - tr*aim);
    }
    __syncthreads();
    const float Dh = Dp_a[l*HH + h];
    __nv_bfloat16* GAh = g_GAh + ((size_t)l*HH + h)*128*256;
    __nv_bfloat16* GAl = g_GAl + ((size_t)l*HH + h)*128*256;
    __nv_bfloat16* GWh = g_GWh + ((size_t)l*HH + h)*128*128;
    __nv_bfloat16* GWl = g_GWl + ((size_t)l*HH + h)*128*128;

    for (int cd = 0; cd < 4; cd++) {
        if (t < 64) {
            float Lr = s_lr[t], Li = s_li[t];
            #pragma unroll
            for (int dd = 0; dd < 32; dd++) {
                s_pr[t][dd] = pr; s_pi[t][dd] = pi;
                float npr = pr*Lr - pi*Li;
                float npi = pr*Li + pi*Lr;
                pr = npr; pi = npi;
            }
        }
        __syncthreads();
        {
            int dd = t >> 2, q = t & 3;
            float part = 0.f;
            for (int n = q*16; n < q*16 + 16; n++)
                part += s_cr[n]*s_pr[n][dd] + s_ci[n]*s_pi[n][dd];
            part += __shfl_xor_sync(0xffffffffu, part, 1);
            part += __shfl_xor_sync(0xffffffffu, part, 2);
            int d = cd*32 + dd;
            if (q == 0) s_k[d] = part + (d == 0 ? Dh : 0.f);
        }
        for (int dd = 0; dd < 32; dd++) {
            int d = cd*32 + dd, r = d - 1;
            if (r >= 0) {
                float v;
                if (t < 64)
                    v = s_cr[t]*s_pr[t][dd] + s_ci[t]*s_pi[t][dd];
                else {
                    int j = t - 64;
                    v = s_ci[j]*s_pr[j][dd] - s_cr[j]*s_pi[j][dd];
                }
                __nv_bfloat16 hb, lb; bsplit(v, hb, lb);
                GAh[r*256 + 128 + t] = hb;
                GAl[r*256 + 128 + t] = lb;
            }
        }
        for (int p = 0; p < 32; p++) {
            int row = p*4 + (t >> 5);
            int sc = t & 31;
            int s = 96 - cd*32 + sc;
            int dd = 31 - sc;
            float v = (row < 64) ? s_pr[row][dd] : s_pi[row-64][dd];
            __nv_bfloat16 hb, lb; bsplit(v, hb, lb);
            GWh[row*128 + s] = hb;
            GWl[row*128 + s] = lb;
        }
        __syncthreads();
    }
    if (t < 64) { s_pr[t][0] = pr; s_pi[t][0] = pi; }
    __syncthreads();
    {
        float v;
        if (t < 64)
            v = s_cr[t]*s_pr[t][0] + s_ci[t]*s_pi[t][0];
        else {
            int j = t - 64;
            v = s_ci[j]*s_pr[j][0] - s_cr[j]*s_pi[j][0];
        }
        __nv_bfloat16 hb, lb; bsplit(v, hb, lb);
        GAh[127*256 + 128 + t] = hb;
        GAl[127*256 + 128 + t] = lb;
    }
    for (int r = 0; r < 128; r++) {
        float v = (t <= r) ? s_k[r - t] : 0.f;
        __nv_bfloat16 hb, lb; bsplit(v, hb, lb);
        GAh[r*256 + t] = hb;
        GAl[r*256 + t] = lb;
    }
}

// ---------------------------------------------------------------------------
// scanfix: compose Zend0 across chunks; write z0 (bf16 hi/lo) into X rows 128+
// ---------------------------------------------------------------------------
__global__ void __launch_bounds__(256) scanfix_kernel(
    const float* __restrict__ log_dt,
    const float* __restrict__ logA_re,
    const float* __restrict__ A_im)
{
    int gid = blockIdx.x*256 + threadIdx.x;
    int n = gid & 63, h = (gid >> 6) & 255, b = gid >> 14;

    float Lr, Li, are, aim;
    s4_lambda(log_dt, logA_re, A_im, h, n, Lr, Li, are, aim);
    #pragma unroll
    for (int s = 0; s < 7; s++) {
        float nr = Lr*Lr - Li*Li, ni = 2.f*Lr*Li;
        Lr = nr; Li = ni;
    }

    const float* zcre = g_zc + (size_t)h*128*MM + n*MM;
    const float* zcim = zcre + 64*MM;
    __nv_bfloat16* Xh = g_Xh + (size_t)h*MM*256;
    __nv_bfloat16* Xl = g_Xl + (size_t)h*MM*256;

    float cr = 0.f, ci = 0.f;
    #pragma unroll
    for (int c = 0; c < NC; c++) {
        int m = b*16 + c;
        __nv_bfloat16 hb, lb;
        bsplit(cr, hb, lb);
        Xh[(size_t)m*256 + 128 + n] = hb; Xl[(size_t)m*256 + 128 + n] = lb;
        bsplit(ci, hb, lb);
        Xh[(size_t)m*256 + 192 + n] = hb; Xl[(size_t)m*256 + 192 + n] = lb;
        float zr = zcre[m], zi = zcim[m];
        float nr = Lr*cr - Li*ci + zr;
        float ni = Lr*ci + Li*cr + zi;
        cr = nr; ci = ni;
    }
}

// ---------------------------------------------------------------------------
// GEMM building blocks
// ---------------------------------------------------------------------------
__device__ __forceinline__ void cp16(u32 dst, const void* src) {
    asm volatile("cp.async.cg.shared.global [%0], [%1], 16;" :: "r"(dst), "l"(src));
}
__device__ __forceinline__ void ldsm4(u32& r0, u32& r1, u32& r2, u32& r3, u32 addr) {
    asm volatile("ldmatrix.sync.aligned.m8n8.x4.shared.b16 {%0,%1,%2,%3},[%4];"
                 : "=r"(r0), "=r"(r1), "=r"(r2), "=r"(r3) : "r"(addr));
}
__device__ __forceinline__ void ldsm4t(u32& r0, u32& r1, u32& r2, u32& r3, u32 addr) {
    asm volatile("ldmatrix.sync.aligned.m8n8.x4.trans.shared.b16 {%0,%1,%2,%3},[%4];"
                 : "=r"(r0), "=r"(r1), "=r"(r2), "=r"(r3) : "r"(addr));
}
__device__ __forceinline__ void mma_bf16(float* d, const u32* a, const u32* b) {
    asm volatile(
        "mma.sync.aligned.m16n8k16.row.col.f32.bf16.bf16.f32 "
        "{%0,%1,%2,%3},{%4,%5,%6,%7},{%8,%9},{%0,%1,%2,%3};"
        : "+f"(d[0]), "+f"(d[1]), "+f"(d[2]), "+f"(d[3])
        : "r"(a[0]), "r"(a[1]), "r"(a[2]), "r"(a[3]), "r"(b[0]), "r"(b[1]));
}

#define STG2 24576

__device__ __forceinline__ float gelu_f(float yv) {
    return 0.5f*yv*(1.0f + erff(yv*0.70710678118654752f));
}

// ---------------------------------------------------------------------------
// gemm_s4: per-channel bf16x3.
//   pass1: Zend0 = G_W*U (K=128) -> g_zc
//   pass2: Y = G_A*X (K=256) -> gelu -> bf16 hi/lo in (h,m,t) layout (g_gh/g_gl)
// ---------------------------------------------------------------------------
__global__ void __launch_bounds__(256) gemm_s4_kernel(int pass, int l)
{
    __shared__ __align__(128) char smem_buf[2*STG2];
    const int h  = blockIdx.y;
    const int mt = blockIdx.x;
    const int tid = threadIdx.x, lane = tid & 31, w = tid >> 5;
    const int wm = w & 3, wn = w >> 2;

    const int NK = (pass == 1) ? 128 : 256;
    const __nv_bfloat16* Ahp = (pass == 1) ? g_GWh + ((size_t)l*HH + h)*128*128
                                           : g_GAh + ((size_t)l*HH + h)*128*256;
    const __nv_bfloat16* Alp = (pass == 1) ? g_GWl + ((size_t)l*HH + h)*128*128
                                           : g_GAl + ((size_t)l*HH + h)*128*256;
    const __nv_bfloat16* Bhp = g_Xh + (size_t)h*MM*256;
    const __nv_bfloat16* Blp = g_Xl + (size_t)h*MM*256;

    const int nch = NK/32;
    const u32 smem_base = (u32)__cvta_generic_to_shared(smem_buf);

    float acc[2][4][4];
    #pragma unroll
    for (int mi = 0; mi < 2; mi++)
        #pragma unroll
        for (int ni = 0; ni < 4; ni++)
            #pragma unroll
            for (int r = 0; r < 4; r++) acc[mi][ni][r] = 0.f;

    auto load_chunk = [&](int kc, int stage) {
        int k0 = kc*32;
        u32 base = smem_base + stage*STG2;
        #pragma unroll
        for (int i = 0; i < 2; i++) {
            int gid = i*256 + tid;
            int row = gid >> 2, g = gid & 3;
            int pg = g ^ ((row >> 1) & 3);
            cp16(base + row*64 + pg*16,        Ahp + (size_t)row*NK + k0 + g*8);
            cp16(base + 8192 + row*64 + pg*16, Alp + (size_t)row*NK + k0 + g*8);
        }
        {
            int row = tid >> 2, g = tid & 3;
            int pg = g ^ ((row >> 1) & 3);
            cp16(base + 16384 + row*64 + pg*16, Bhp + (size_t)(mt*64 + row)*256 + k0 + g*8);
            cp16(base + 20480 + row*64 + pg*16, Blp + (size_t)(mt*64 + row)*256 + k0 + g*8);
        }
    };

    load_chunk(0, 0);
    asm volatile("cp.async.commit_group;");

    for (int kc = 0; kc < nch; kc++) {
        if (kc + 1 < nch) load_chunk(kc + 1, (kc + 1) & 1);
        asm volatile("cp.async.commit_group;");
        asm volatile("cp.async.wait_group 1;");
        __syncthreads();

        const u32 ab  = smem_base + (kc & 1)*STG2;
        const u32 alb = ab + 8192, bhb = ab + 16384, blb = ab + 20480;

        #pragma unroll
        for (int ks = 0; ks < 2; ks++) {
            const int grp = lane >> 3, rh = lane & 7;
            u32 ah[2][4], al[2][4];
            #pragma unroll
            for (int mi = 0; mi < 2; mi++) {
                int row = wm*32 + mi*16 + rh + (grp & 1)*8;
                int kg  = 2*ks + (grp >> 1);
                u32 off = row*64 + ((kg ^ ((row >> 1) & 3))*16);
                ldsm4(ah[mi][0], ah[mi][1], ah[mi][2], ah[mi][3], ab + off);
                ldsm4(al[mi][0], al[mi][1], al[mi][2], al[mi][3], alb + off);
            }
            u32 bh[4][2], bl[4][2];
            #pragma unroll
            for (int nf = 0; nf < 2; nf++) {
                int row = wn*32 + nf*16 + rh + (grp >> 1)*8;
                int kg  = 2*ks + (grp & 1);
                u32 off = row*64 + ((kg ^ ((row >> 1) & 3))*16);
                u32 r0, r1, r2, r3;
                ldsm4(r0, r1, r2, r3, bhb + off);
                bh[nf*2][0] = r0; bh[nf*2][1] = r1;
                bh[nf*2+1][0] = r2; bh[nf*2+1][1] = r3;
                ldsm4(r0, r1, r2, r3, blb + off);
                bl[nf*2][0] = r0; bl[nf*2][1] = r1;
                bl[nf*2+1][0] = r2; bl[nf*2+1][1] = r3;
            }
            #pragma unroll
            for (int mi = 0; mi < 2; mi++)
                #pragma unroll
                for (int ni = 0; ni < 4; ni++) {
                    mma_bf16(acc[mi][ni], ah[mi], bh[ni]);
                    mma_bf16(acc[mi][ni], al[mi], bh[ni]);
                    mma_bf16(acc[mi][ni], ah[mi], bl[ni]);
                }
        }
        __syncthreads();
    }

    const int lq = lane >> 2, lc = lane & 3;
    if (pass == 1) {
        float* outp = g_zc + (size_t)h*128*MM;
        #pragma unroll
        for (int mi = 0; mi < 2; mi++) {
            #pragma unroll
            for (int ni = 0; ni < 4; ni++) {
                int row = wm*32 + mi*16 + lq;
                int col = mt*64 + wn*32 + ni*8 + lc*2;
                float2 v0; v0.x = acc[mi][ni][0]; v0.y = acc[mi][ni][1];
                float2 v1; v1.x = acc[mi][ni][2]; v1.y = acc[mi][ni][3];
                *(float2*)(outp + (size_t)row*MM + col) = v0;
                *(float2*)(outp + (size_t)(row+8)*MM + col) = v1;
            }
        }
    } else {
        // Epilogue: transpose in smem -> gelu -> bf16 hi/lo (h,m,t) layout
        float* sep = (float*)smem_buf;          // [m 64][t 130]
        #pragma unroll
        for (int mi = 0; mi < 2; mi++) {
            #pragma unroll
            for (int ni = 0; ni < 4; ni++) {
                int t  = wm*32 + mi*16 + lq;
                int ml = wn*32 + ni*8 + lc*2;
                sep[ml*130 + t]          = acc[mi][ni][0];
                sep[(ml+1)*130 + t]      = acc[mi][ni][1];
                sep[ml*130 + t + 8]      = acc[mi][ni][2];
                sep[(ml+1)*130 + t + 8]  = acc[mi][ni][3];
            }
        }
        __syncthreads();
        const int ml = tid >> 2, tq = tid & 3;
        size_t dst = (size_t)h*((size_t)MM*128) + (size_t)(mt*64 + ml)*128 + tq*32;
        union P4 { __nv_bfloat16 b[4]; ull u; };
        #pragma unroll
        for (int j4 = 0; j4 < 8; j4++) {
            P4 ph, pl;
            #pragma unroll
            for (int i = 0; i < 4; i++) {
                float gv = gelu_f(sep[ml*130 + tq*32 + j4*4 + i]);
                bsplit(gv, ph.b[i], pl.b[i]);
            }
            *(ull*)(g_gh + dst + j4*4) = ph.u;
            *(ull*)(g_gl + dst + j4*4) = pl.u;
        }
    }
}

// ---------------------------------------------------------------------------
// GLU GEMM: bf16x3, 128m x 64 gemm-cols, static 48KB smem.
//   A read from (h, m, t) layout via ldmatrix.trans; one m-chunk per m-tile.
//   Fused GLU+bias+residual epilogue.
// ---------------------------------------------------------------------------
__global__ void __launch_bounds__(256) gemm_glu_kernel(int l, const float* __restrict__ bias)
{
    __shared__ __align__(128) char smem_buf[2*STG2];

    const int mch = blockIdx.y;          // m-chunk: global rows mch*128 + t
    const int nb  = blockIdx.x;
    const int tid = threadIdx.x;
    const int lane = tid & 31, w = tid >> 5;
    const int wm = w & 3;
    const int wn = w >> 2;

    const __nv_bfloat16* Whp = g_wh + (size_t)l*GN*GK;
    const __nv_bfloat16* Wlp = g_wl + (size_t)l*GN*GK;
    const __nv_bfloat16* Ahp = g_gh + (size_t)mch*128;   // + h*MM*128
    const __nv_bfloat16* Alp = g_gl + (size_t)mch*128;

    const u32 smem_base = (u32)__cvta_generic_to_shared(smem_buf);

    float acc[2][4][4];
    #pragma unroll
    for (int mi = 0; mi < 2; mi++)
        #pragma unroll
        for (int ni = 0; ni < 4; ni++)
            #pragma unroll
            for (int r = 0; r < 4; r++) acc[mi][ni][r] = 0.f;

    // A smem layout per stage: [k 32][t 128] bf16 = 32 rows x 256B, swizzle g^(k&7)
    auto load_chunk = [&](int kc, int stage) {
        int k0 = kc*32;
        u32 base = smem_base + stage*STG2;
        #pragma unroll
        for (int i = 0; i < 2; i++) {
            int gid = i*256 + tid;
            int krow = gid >> 4, g = gid & 15;
            int pg = g ^ (krow & 7);
            cp16(base + krow*256 + pg*16,
                 Ahp + (size_t)(k0 + krow)*((size_t)MM*128) + g*8);
            cp16(base + 8192 + krow*256 + pg*16,
                 Alp + (size_t)(k0 + krow)*((size_t)MM*128) + g*8);
        }
        {
            int row = tid >> 2, g = tid & 3;
            int pg = g ^ ((row >> 1) & 3);
            int wr = nb*32 + (row >> 1) + (row & 1)*256;
            cp16(base + 16384 + row*64 + pg*16, Whp + (size_t)wr*GK + k0 + g*8);
            cp16(base + 20480 + row*64 + pg*16, Wlp + (size_t)wr*GK + k0 + g*8);
        }
    };

    load_chunk(0, 0);
    asm volatile("cp.async.commit_group;");

    #pragma unroll 1
    for (int kc = 0; kc < 8; kc++) {
        if (kc + 1 < 8) load_chunk(kc + 1, (kc + 1) & 1);
        asm volatile("cp.async.commit_group;");
        asm volatile("cp.async.wait_group 1;");
        __syncthreads();

        const u32 ab  = smem_base + (kc & 1)*STG2;
        const u32 alb = ab + 8192, bhb = ab + 16384, blb = ab + 20480;

        #pragma unroll
        for (int ks = 0; ks < 2; ks++) {
            const int grp = lane >> 3, rh = lane & 7;
            // A via ldmatrix.trans from [k][t]: group -> (t-block=grp&1, k-block=grp>>1)
            u32 ah[2][4], al[2][4];
            #pragma unroll
            for (int mi = 0; mi < 2; mi++) {
                int tb   = wm*32 + mi*16;
                int krow = ks*16 + (grp >> 1)*8 + rh;
                int g    = (tb >> 3) + (grp & 1);
                u32 off  = krow*256 + ((g ^ (krow & 7))*16);
                ldsm4t(ah[mi][0], ah[mi][1], ah[mi][2], ah[mi][3], ab + off);
                ldsm4t(al[mi][0], al[mi][1], al[mi][2], al[mi][3], alb + off);
            }
            u32 bh[4][2], bl[4][2];
            #pragma unroll
            for (int nf = 0; nf < 2; nf++) {
                int row = wn*32 + nf*16 + rh + (grp >> 1)*8;
                int kg  = 2*ks + (grp & 1);
                u32 off = row*64 + ((kg ^ ((row >> 1) & 3))*16);
                u32 r0, r1, r2, r3;
                ldsm4(r0, r1, r2, r3, bhb + off);
                bh[nf*2][0] = r0; bh[nf*2][1] = r1;
                bh[nf*2+1][0] = r2; bh[nf*2+1][1] = r3;
                ldsm4(r0, r1, r2, r3, blb + off);
                bl[nf*2][0] = r0; bl[nf*2][1] = r1;
                bl[nf*2+1][0] = r2; bl[nf*2+1][1] = r3;
            }
            #pragma unroll
            for (int mi = 0; mi < 2; mi++)
                #pragma unroll
                for (int ni = 0; ni < 4; ni++) {
                    mma_bf16(acc[mi][ni], ah[mi], bh[ni]);
                    mma_bf16(acc[mi][ni], al[mi], bh[ni]);
                    mma_bf16(acc[mi][ni], ah[mi], bl[ni]);
                }
        }
        __syncthreads();
    }

    const int lc = lane & 3, lq = lane >> 2;
    const int m0 = mch*128;
    #pragma unroll
    for (int ni = 0; ni < 4; ni++) {
        const int oc = nb*32 + wn*16 + ni*4 + lc;
        const float bL = bias[oc];
        const float bR = bias[oc + 256];
        #pragma unroll
        for (int mi = 0; mi < 2; mi++) {
            int mg = m0 + wm*32 + mi*16 + lq;
            {
                float zl = acc[mi][ni][0] + bL;
                float zr_ = acc[mi][ni][1] + bR;
                float sv = zl * (1.0f/(1.0f + expf(-zr_))) + g_x[(size_t)mg*HH + oc];
                g_s[(size_t)mg*HH + oc] = sv;
            }
            {
                int mg2 = mg + 8;
                float zl = acc[mi][ni][2] + bL;
                float zr_ = acc[mi][ni][3] + bR;
                float sv = zl * (1.0f/(1.0f + expf(-zr_))) + g_x[(size_t)mg2*HH + oc];
                g_s[(size_t)mg2*HH + oc] = sv;
            }
        }
    }
}

// ---------------------------------------------------------------------------
// ln_fused: LayerNorm + (mode&1) coalesced transpose-to-X + (mode&2) heads.
// ---------------------------------------------------------------------------
__device__ __forceinline__ float softplus_f(float x) {
    return fmaxf(x, 0.f) + log1pf(expf(-fabsf(x)));
}

__global__ void __launch_bounds__(256) ln_fused_kernel(
    const float* __restrict__ lng, const float* __restrict__ lnb,
    const float* __restrict__ mu_w, const float* __restrict__ mu_b,
    const float* __restrict__ al_w, const float* __restrict__ al_b,
    float* __restrict__ out, int half, int mode)
{
    __shared__ float ysT[256][33];     // [h][t]
    const int wi = threadIdx.x >> 5, lane = threadIdx.x & 31;
    const int r0 = blockIdx.x*32;

    #pragma unroll
    for (int it = 0; it < 4; it++) {
        int rl = wi + it*8;
        size_t row = (size_t)(r0 + rl);
        const float4* sp = (const float4*)(g_s + row*HH);
        float4 v0 = sp[lane];
        float4 v1 = sp[lane + 32];

        float s1 = v0.x+v0.y+v0.z+v0.w + v1.x+v1.y+v1.z+v1.w;
        float s2 = v0.x*v0.x+v0.y*v0.y+v0.z*v0.z+v0.w*v0.w
                 + v1.x*v1.x+v1.y*v1.y+v1.z*v1.z+v1.w*v1.w;
        #pragma unroll
        for (int o = 16; o > 0; o >>= 1) {
            s1 += __shfl_xor_sync(0xffffffffu, s1, o);
            s2 += __shfl_xor_sync(0xffffffffu, s2, o);
        }
        float mean = s1 * (1.0f/HH);
        float var  = s2 * (1.0f/HH) - mean*mean;
        float inv  = rsqrtf(var + 1e-5f);

        const float4* gp = (const float4*)lng;
        const float4* bp = (const float4*)lnb;
        float4 g0 = gp[lane], g1 = gp[lane+32];
        float4 b0 = bp[lane], b1 = bp[lane+32];
        float4 y0, y1;
        y0.x = (v0.x-mean)*inv*g0.x + b0.x;  y0.y = (v0.y-mean)*inv*g0.y + b0.y;
        y0.z = (v0.z-mean)*inv*g0.z + b0.z;  y0.w = (v0.w-mean)*inv*g0.w + b0.w;
        y1.x = (v1.x-mean)*inv*g1.x + b1.x;  y1.y = (v1.y-mean)*inv*g1.y + b1.y;
        y1.z = (v1.z-mean)*inv*g1.z + b1.z;  y1.w = (v1.w-mean)*inv*g1.w + b1.w;

        float4* xp = (float4*)(g_x + row*HH);
        xp[lane] = y0;
        xp[lane + 32] = y1;

        if (mode & 1) {
            int hb0 = lane*4;
            ysT[hb0+0][rl] = y0.x; ysT[hb0+1][rl] = y0.y;
            ysT[hb0+2][rl] = y0.z; ysT[hb0+3][rl] = y0.w;
            ysT[128+hb0+0][rl] = y1.x; ysT[128+hb0+1][rl] = y1.y;
            ysT[128+hb0+2][rl] = y1.z; ysT[128+hb0+3][rl] = y1.w;
        }

        if (mode & 2) {
            const float4* mp = (const float4*)mu_w;
            const float4* ap = (const float4*)al_w;
            float4 m0 = mp[lane], m1 = mp[lane+32];
            float4 a0 = ap[lane], a1 = ap[lane+32];
            float sm = y0.x*m0.x + y0.y*m0.y + y0.z*m0.z + y0.w*m0.w
                     + y1.x*m1.x + y1.y*m1.y + y1.z*m1.z + y1.w*m1.w;
            float sa = y0.x*a0.x + y0.y*a0.y + y0.z*a0.z + y0.w*a0.w
                     + y1.x*a1.x + y1.y*a1.y + y1.z*a1.z + y1.w*a1.w;
            #pragma unroll
            for (int o = 16; o > 0; o >>= 1) {
                sm += __shfl_xor_sync(0xffffffffu, sm, o);
                sa += __shfl_xor_sync(0xffffffffu, sa, o);
            }
            if (lane == 0) {
                out[row]        = softplus_f(sm + mu_b[0]);
                out[half + row] = softplus_f(sa + al_b[0]);
            }
        }
    }

    if (mode & 1) {
        __syncthreads();
        const int m = r0 >> 7, tb = r0 & 127;
        union P4 { __nv_bfloat16 b[4]; ull u; };
        #pragma unroll
        for (int p = 0; p < 8; p++) {
            int h  = p*32 + wi*4 + (lane >> 3);
            int tq = lane & 7;
            P4 ph, pl;
            #pragma unroll
            for (int i = 0; i < 4; i++) bsplit(ysT[h][tq*4 + i], ph.b[i], pl.b[i]);
            size_t dst = (size_t)h*((size_t)MM*256) + (size_t)m*256 + tb + tq*4;
            *(ull*)(g_Xh + dst) = ph.u;
            *(ull*)(g_Xl + dst) = pl.u;
        }
    }
}

// ---------------------------------------------------------------------------
extern "C" void kernel_launch(void* const* d_in, const int* in_sizes, int n_in,
                              void* d_out, int out_size)
{
    const float* x      = (const float*)d_in[0];
    const float* enc_w  = (const float*)d_in[1];
    const float* enc_b  = (const float*)d_in[2];
    const float* log_dt = (const float*)d_in[3];
    const float* logA   = (const float*)d_in[4];
    const float* A_im   = (const float*)d_in[5];
    const float* C_re   = (const float*)d_in[6];
    const float* C_im   = (const float*)d_in[7];
    const float* Dp     = (const float*)d_in[8];
    const float* out_w  = (const float*)d_in[9];
    const float* out_b  = (const float*)d_in[10];
    const float* ln_g   = (const float*)d_in[11];
    const float* ln_b   = (const float*)d_in[12];
    const float* mu_w   = (const float*)d_in[13];
    const float* mu_b   = (const float*)d_in[14];
    const float* al_w   = (const float*)d_in[15];
    const float* al_b   = (const float*)d_in[16];
    float* out = (float*)d_out;

    enc_kernel<<<GM, HH>>>(x, enc_w, enc_b);
    wconv_kernel<<<(NLAYERS*GN*GK)/256, 256>>>(out_w);
    genG_all_kernel<<<dim3(HH, NLAYERS), 128>>>(log_dt, logA, A_im, C_re, C_im, Dp);
    fwdT_kernel<<<dim3(MM, 8), 256>>>();     // X for layer 0 only

    for (int l = 0; l < NLAYERS; l++) {
        const float* ldt = log_dt + l*HH;
        const float* lA  = logA   + (size_t)l*HH*NN;
        const float* Ai  = A_im   + (size_t)l*HH*NN;

        gemm_s4_kernel<<<dim3(4, HH), 256>>>(1, l);
        scanfix_kernel<<<(BB*HH*NN)/256, 256>>>(ldt, lA, Ai);
        gemm_s4_kernel<<<dim3(4, HH), 256>>>(2, l);
        gemm_glu_kernel<<<dim3(8, GM/128), 256>>>(l, out_b + (size_t)l*GN);
        ln_fused_kernel<<<GM/32, 256>>>(ln_g + l*HH, ln_b + l*HH,
                                        mu_w, mu_b, al_w, al_b,
                                        out, out_size/2,
                                        (l == NLAYERS-1) ? 2 : 1);
    }
}

// round 14
// speedup vs baseline: 1.2941x; 1.1573x over previous
#include <cuda_runtime.h>
#include <cuda_bf16.h>
#include <math.h>

// Problem constants
#define BB 16
#define LL 2048
#define DIN 8
#define HH 256
#define NN 64
#define NLAYERS 4
#define GM (BB*LL)      // 32768 rows
#define GK HH           // 256
#define GN (2*HH)       // 512
#define NC 16           // time chunks
#define TT (LL/NC)      // 128
#define MM (BB*NC)      // 256 chunk-columns

typedef unsigned long long ull;
typedef unsigned int u32;

// Scratch (device globals)
__device__ float g_x[(size_t)GM*HH];                       // activations (row,h)
__device__ float g_s[(size_t)GM*HH];                       // pre-LN (row,h)
__device__ __nv_bfloat16 g_gh[(size_t)GM*HH];              // gelu out hi, (h,m,t) layout
__device__ __nv_bfloat16 g_gl[(size_t)GM*HH];              // gelu out lo, (h,m,t) layout
__device__ __nv_bfloat16 g_wh[(size_t)NLAYERS*GN*GK];      // GLU W hi
__device__ __nv_bfloat16 g_wl[(size_t)NLAYERS*GN*GK];      // GLU W lo
__device__ __nv_bfloat16 g_Xh[(size_t)HH*MM*256];          // X=[u;z0] hi (h,m,k)
__device__ __nv_bfloat16 g_Xl[(size_t)HH*MM*256];          // X lo
__device__ __nv_bfloat16 g_GAh[(size_t)NLAYERS*HH*128*256];// [K|V] hi (l,h,r,k)
__device__ __nv_bfloat16 g_GAl[(size_t)NLAYERS*HH*128*256];
__device__ __nv_bfloat16 g_GWh[(size_t)NLAYERS*HH*128*128];// W hi (l,h,i,s)
__device__ __nv_bfloat16 g_GWl[(size_t)NLAYERS*HH*128*128];

__device__ __forceinline__ void bsplit(float v, __nv_bfloat16& h, __nv_bfloat16& l) {
    h = __float2bfloat16_rn(v);
    l = __float2bfloat16_rn(v - __bfloat162float(h));
}

// ---------------------------------------------------------------------------
// Encoder (row,h)
// ---------------------------------------------------------------------------
__global__ void enc_kernel(const float* __restrict__ x,
                           const float* __restrict__ w,
                           const float* __restrict__ b)
{
    int row = blockIdx.x;
    int h = threadIdx.x;
    __shared__ float xr[DIN];
    if (h < DIN) xr[h] = x[row*DIN + h];
    __syncthreads();
    float s = b[h];
    #pragma unroll
    for (int k = 0; k < DIN; k++)
        s = fmaf(xr[k], w[h*DIN + k], s);
    g_x[(size_t)row*HH + h] = s;
}

// ---------------------------------------------------------------------------
// One-shot GLU W -> bf16 hi/lo split
// ---------------------------------------------------------------------------
__global__ void wconv_kernel(const float* __restrict__ W)
{
    size_t i = (size_t)blockIdx.x*256 + threadIdx.x;
    float w = W[i];
    bsplit(w, g_wh[i], g_wl[i]);
}

// ---------------------------------------------------------------------------
__device__ __forceinline__ void s4_lambda(
    const float* log_dt, const float* logA_re, const float* A_im,
    int h, int n, float& Lr, float& Li, float& are, float& aim)
{
    float dt = expf(log_dt[h]);
    are = -expf(logA_re[h*NN + n]);
    aim = A_im[h*NN + n];
    float er = expf(dt*are);
    float dim = dt*aim;
    Lr = er*cosf(dim);
    Li = er*sinf(dim);
}

// ---------------------------------------------------------------------------
// fwdT: g_x (row,h) fp32 -> X (h, m, t) bf16 hi/lo. Layer-0 only.
// ---------------------------------------------------------------------------
__global__ void __launch_bounds__(256) fwdT_kernel()
{
    const int m = blockIdx.x, h0 = blockIdx.y*32;
    const int b = m >> 4, c = m & 15;
    const size_t rbase = ((size_t)b*LL + c*TT)*HH;
    __shared__ float sT[128][33];
    const int tid = threadIdx.x;
    const int hl = (tid & 7)*4, tr0 = tid >> 3;
    #pragma unroll
    for (int p = 0; p < 4; p++) {
        int tt = p*32 + tr0;
        float4 v = *(const float4*)(g_x + rbase + (size_t)tt*HH + h0 + hl);
        sT[tt][hl] = v.x; sT[tt][hl+1] = v.y; sT[tt][hl+2] = v.z; sT[tt][hl+3] = v.w;
    }
    __syncthreads();
    const int w = tid >> 5, lane = tid & 31;
    union P4 { __nv_bfloat16 b[4]; ull u; };
    #pragma unroll
    for (int p = 0; p < 4; p++) {
        int hh = p*8 + w;
        int t0 = lane*4;
        P4 ph, pl;
        #pragma unroll
        for (int i = 0; i < 4; i++) bsplit(sT[t0+i][hh], ph.b[i], pl.b[i]);
        size_t dst = (size_t)(h0+hh)*((size_t)MM*256) + (size_t)m*256 + t0;
        *(ull*)(g_Xh + dst) = ph.u;
        *(ull*)(g_Xl + dst) = pl.u;
    }
}

// ---------------------------------------------------------------------------
// genG_all: per-(layer,channel) G_A=[K|V] (128x256), G_W (128x128), bf16 hi/lo.
// ---------------------------------------------------------------------------
__global__ void __launch_bounds__(128) genG_all_kernel(
    const float* __restrict__ log_dt_a,
    const float* __restrict__ logA_a,
    const float* __restrict__ A_im_a,
    const float* __restrict__ C_re_a,
    const float* __restrict__ C_im_a,
    const float* __restrict__ Dp_a)
{
    const int h = blockIdx.x;
    const int l = blockIdx.y;
    const int t = threadIdx.x;
    const float* log_dt = log_dt_a + l*HH;
    const float* logA_re = logA_a + (size_t)l*HH*NN;
    const float* A_im = A_im_a + (size_t)l*HH*NN;
    const float* C_re = C_re_a + (size_t)l*HH*NN;
    const float* C_im = C_im_a + (size_t)l*HH*NN;

    __shared__ float s_cr[64], s_ci[64], s_lr[64], s_li[64];
    __shared__ float s_pr[64][33], s_pi[64][33];
    __shared__ float s_k[128];

    float pr = 1.f, pi = 0.f;
    if (t < 64) {
        float are, aim, Lr, Li;
        s4_lambda(log_dt, logA_re, A_im, h, t, Lr, Li, are, aim);
        s_lr[t] = Lr; s_li[t] = Li;
        float Cre = C_re[h*NN + t], Cim = C_im[h*NN + t];
        float nr = Lr - 1.f, ni = Li;
        float tr = Cre*nr - Cim*ni, ti = Cre*ni + Cim*nr;
        float inv = 2.f/(are*are + aim*aim);
        s_cr[t] =  inv*(tr*are + ti*aim);
        s_ci[t] = -inv*(ti*are - tr*aim);
    }
    __syncthreads();
    const float Dh = Dp_a[l*HH + h];
    __nv_bfloat16* GAh = g_GAh + ((size_t)l*HH + h)*128*256;
    __nv_bfloat16* GAl = g_GAl + ((size_t)l*HH + h)*128*256;
    __nv_bfloat16* GWh = g_GWh + ((size_t)l*HH + h)*128*128;
    __nv_bfloat16* GWl = g_GWl + ((size_t)l*HH + h)*128*128;

    for (int cd = 0; cd < 4; cd++) {
        if (t < 64) {
            float Lr = s_lr[t], Li = s_li[t];
            #pragma unroll
            for (int dd = 0; dd < 32; dd++) {
                s_pr[t][dd] = pr; s_pi[t][dd] = pi;
                float npr = pr*Lr - pi*Li;
                float npi = pr*Li + pi*Lr;
                pr = npr; pi = npi;
            }
        }
        __syncthreads();
        {
            int dd = t >> 2, q = t & 3;
            float part = 0.f;
            for (int n = q*16; n < q*16 + 16; n++)
                part += s_cr[n]*s_pr[n][dd] + s_ci[n]*s_pi[n][dd];
            part += __shfl_xor_sync(0xffffffffu, part, 1);
            part += __shfl_xor_sync(0xffffffffu, part, 2);
            int d = cd*32 + dd;
            if (q == 0) s_k[d] = part + (d == 0 ? Dh : 0.f);
        }
        for (int dd = 0; dd < 32; dd++) {
            int d = cd*32 + dd, r = d - 1;
            if (r >= 0) {
                float v;
                if (t < 64)
                    v = s_cr[t]*s_pr[t][dd] + s_ci[t]*s_pi[t][dd];
                else {
                    int j = t - 64;
                    v = s_ci[j]*s_pr[j][dd] - s_cr[j]*s_pi[j][dd];
                }
                __nv_bfloat16 hb, lb; bsplit(v, hb, lb);
                GAh[r*256 + 128 + t] = hb;
                GAl[r*256 + 128 + t] = lb;
            }
        }
        for (int p = 0; p < 32; p++) {
            int row = p*4 + (t >> 5);
            int sc = t & 31;
            int s = 96 - cd*32 + sc;
            int dd = 31 - sc;
            float v = (row < 64) ? s_pr[row][dd] : s_pi[row-64][dd];
            __nv_bfloat16 hb, lb; bsplit(v, hb, lb);
            GWh[row*128 + s] = hb;
            GWl[row*128 + s] = lb;
        }
        __syncthreads();
    }
    if (t < 64) { s_pr[t][0] = pr; s_pi[t][0] = pi; }
    __syncthreads();
    {
        float v;
        if (t < 64)
            v = s_cr[t]*s_pr[t][0] + s_ci[t]*s_pi[t][0];
        else {
            int j = t - 64;
            v = s_ci[j]*s_pr[j][0] - s_cr[j]*s_pi[j][0];
        }
        __nv_bfloat16 hb, lb; bsplit(v, hb, lb);
        GAh[127*256 + 128 + t] = hb;
        GAl[127*256 + 128 + t] = lb;
    }
    for (int r = 0; r < 128; r++) {
        float v = (t <= r) ? s_k[r - t] : 0.f;
        __nv_bfloat16 hb, lb; bsplit(v, hb, lb);
        GAh[r*256 + t] = hb;
        GAl[r*256 + t] = lb;
    }
}

// ---------------------------------------------------------------------------
// GEMM building blocks
// ---------------------------------------------------------------------------
__device__ __forceinline__ void cp16(u32 dst, const void* src) {
    asm volatile("cp.async.cg.shared.global [%0], [%1], 16;" :: "r"(dst), "l"(src));
}
__device__ __forceinline__ void ldsm4(u32& r0, u32& r1, u32& r2, u32& r3, u32 addr) {
    asm volatile("ldmatrix.sync.aligned.m8n8.x4.shared.b16 {%0,%1,%2,%3},[%4];"
                 : "=r"(r0), "=r"(r1), "=r"(r2), "=r"(r3) : "r"(addr));
}
__device__ __forceinline__ void ldsm4t(u32& r0, u32& r1, u32& r2, u32& r3, u32 addr) {
    asm volatile("ldmatrix.sync.aligned.m8n8.x4.trans.shared.b16 {%0,%1,%2,%3},[%4];"
                 : "=r"(r0), "=r"(r1), "=r"(r2), "=r"(r3) : "r"(addr));
}
__device__ __forceinline__ void mma_bf16(float* d, const u32* a, const u32* b) {
    asm volatile(
        "mma.sync.aligned.m16n8k16.row.col.f32.bf16.bf16.f32 "
        "{%0,%1,%2,%3},{%4,%5,%6,%7},{%8,%9},{%0,%1,%2,%3};"
        : "+f"(d[0]), "+f"(d[1]), "+f"(d[2]), "+f"(d[3])
        : "r"(a[0]), "r"(a[1]), "r"(a[2]), "r"(a[3]), "r"(b[0]), "r"(b[1]));
}

#define STG2 24576

__device__ __forceinline__ float gelu_f(float yv) {
    return 0.5f*yv*(1.0f + erff(yv*0.70710678118654752f));
}

// ---------------------------------------------------------------------------
// gemm_s4: per-channel bf16x3.
//   pass1: Zend0 = G_W*U (K=128) -> in-block chunk composition (fused scanfix)
//          -> z0 (bf16 hi/lo) into X rows 128+  [each mt tile = 4 full batches]
//   pass2: Y = G_A*X (K=256) -> gelu -> bf16 hi/lo in (h,m,t) layout
// ---------------------------------------------------------------------------
__global__ void __launch_bounds__(256) gemm_s4_kernel(
    int pass, int l,
    const float* __restrict__ log_dt,
    const float* __restrict__ logA_re,
    const float* __restrict__ A_im)
{
    __shared__ __align__(128) char smem_buf[2*STG2];
    const int h  = blockIdx.y;
    const int mt = blockIdx.x;
    const int tid = threadIdx.x, lane = tid & 31, w = tid >> 5;
    const int wm = w & 3, wn = w >> 2;

    const int NK = (pass == 1) ? 128 : 256;
    const __nv_bfloat16* Ahp = (pass == 1) ? g_GWh + ((size_t)l*HH + h)*128*128
                                           : g_GAh + ((size_t)l*HH + h)*128*256;
    const __nv_bfloat16* Alp = (pass == 1) ? g_GWl + ((size_t)l*HH + h)*128*128
                                           : g_GAl + ((size_t)l*HH + h)*128*256;
    const __nv_bfloat16* Bhp = g_Xh + (size_t)h*MM*256;
    const __nv_bfloat16* Blp = g_Xl + (size_t)h*MM*256;

    const int nch = NK/32;
    const u32 smem_base = (u32)__cvta_generic_to_shared(smem_buf);

    float acc[2][4][4];
    #pragma unroll
    for (int mi = 0; mi < 2; mi++)
        #pragma unroll
        for (int ni = 0; ni < 4; ni++)
            #pragma unroll
            for (int r = 0; r < 4; r++) acc[mi][ni][r] = 0.f;

    auto load_chunk = [&](int kc, int stage) {
        int k0 = kc*32;
        u32 base = smem_base + stage*STG2;
        #pragma unroll
        for (int i = 0; i < 2; i++) {
            int gid = i*256 + tid;
            int row = gid >> 2, g = gid & 3;
            int pg = g ^ ((row >> 1) & 3);
            cp16(base + row*64 + pg*16,        Ahp + (size_t)row*NK + k0 + g*8);
            cp16(base + 8192 + row*64 + pg*16, Alp + (size_t)row*NK + k0 + g*8);
        }
        {
            int row = tid >> 2, g = tid & 3;
            int pg = g ^ ((row >> 1) & 3);
            cp16(base + 16384 + row*64 + pg*16, Bhp + (size_t)(mt*64 + row)*256 + k0 + g*8);
            cp16(base + 20480 + row*64 + pg*16, Blp + (size_t)(mt*64 + row)*256 + k0 + g*8);
        }
    };

    load_chunk(0, 0);
    asm volatile("cp.async.commit_group;");

    for (int kc = 0; kc < nch; kc++) {
        if (kc + 1 < nch) load_chunk(kc + 1, (kc + 1) & 1);
        asm volatile("cp.async.commit_group;");
        asm volatile("cp.async.wait_group 1;");
        __syncthreads();

        const u32 ab  = smem_base + (kc & 1)*STG2;
        const u32 alb = ab + 8192, bhb = ab + 16384, blb = ab + 20480;

        #pragma unroll
        for (int ks = 0; ks < 2; ks++) {
            const int grp = lane >> 3, rh = lane & 7;
            u32 ah[2][4], al[2][4];
            #pragma unroll
            for (int mi = 0; mi < 2; mi++) {
                int row = wm*32 + mi*16 + rh + (grp & 1)*8;
                int kg  = 2*ks + (grp >> 1);
                u32 off = row*64 + ((kg ^ ((row >> 1) & 3))*16);
                ldsm4(ah[mi][0], ah[mi][1], ah[mi][2], ah[mi][3], ab + off);
                ldsm4(al[mi][0], al[mi][1], al[mi][2], al[mi][3], alb + off);
            }
            u32 bh[4][2], bl[4][2];
            #pragma unroll
            for (int nf = 0; nf < 2; nf++) {
                int row = wn*32 + nf*16 + rh + (grp >> 1)*8;
                int kg  = 2*ks + (grp & 1);
                u32 off = row*64 + ((kg ^ ((row >> 1) & 3))*16);
                u32 r0, r1, r2, r3;
                ldsm4(r0, r1, r2, r3, bhb + off);
                bh[nf*2][0] = r0; bh[nf*2][1] = r1;
                bh[nf*2+1][0] = r2; bh[nf*2+1][1] = r3;
                ldsm4(r0, r1, r2, r3, blb + off);
                bl[nf*2][0] = r0; bl[nf*2][1] = r1;
                bl[nf*2+1][0] = r2; bl[nf*2+1][1] = r3;
            }
            #pragma unroll
            for (int mi = 0; mi < 2; mi++)
                #pragma unroll
                for (int ni = 0; ni < 4; ni++) {
                    mma_bf16(acc[mi][ni], ah[mi], bh[ni]);
                    mma_bf16(acc[mi][ni], al[mi], bh[ni]);
                    mma_bf16(acc[mi][ni], ah[mi], bl[ni]);
                }
        }
        __syncthreads();
    }

    const int lq = lane >> 2, lc = lane & 3;
    if (pass == 1) {
        // Fused scanfix: stage Zend0 [128 rows][64 m] in smem, compose per (n,b).
        float* sepz = (float*)smem_buf;       // [128][68]
        #pragma unroll
        for (int mi = 0; mi < 2; mi++) {
            #pragma unroll
            for (int ni = 0; ni < 4; ni++) {
                int row = wm*32 + mi*16 + lq;
                int col = wn*32 + ni*8 + lc*2;
                sepz[row*68 + col]       = acc[mi][ni][0];
                sepz[row*68 + col + 1]   = acc[mi][ni][1];
                sepz[(row+8)*68 + col]   = acc[mi][ni][2];
                sepz[(row+8)*68 + col+1] = acc[mi][ni][3];
            }
        }
        __syncthreads();

        const int n = tid & 63, bloc = tid >> 6;      // 4 batches per mt tile
        float Lr, Li, are, aim;
        s4_lambda(log_dt, logA_re, A_im, h, n, Lr, Li, are, aim);
        #pragma unroll
        for (int s = 0; s < 7; s++) {                 // lambda^128
            float nr2 = Lr*Lr - Li*Li, ni2 = 2.f*Lr*Li;
            Lr = nr2; Li = ni2;
        }
        __nv_bfloat16* Xh = g_Xh + (size_t)h*MM*256;
        __nv_bfloat16* Xl = g_Xl + (size_t)h*MM*256;
        float cr = 0.f, ci = 0.f;
        #pragma unroll
        for (int c = 0; c < NC; c++) {
            int mloc = bloc*16 + c;
            size_t mg = (size_t)(mt*64 + mloc);
            __nv_bfloat16 hb, lb;
            bsplit(cr, hb, lb);
            Xh[mg*256 + 128 + n] = hb; Xl[mg*256 + 128 + n] = lb;
            bsplit(ci, hb, lb);
            Xh[mg*256 + 192 + n] = hb; Xl[mg*256 + 192 + n] = lb;
            float zr = sepz[n*68 + mloc];
            float zi = sepz[(n+64)*68 + mloc];
            float nr2 = Lr*cr - Li*ci + zr;
            float ni2 = Lr*ci + Li*cr + zi;
            cr = nr2; ci = ni2;
        }
    } else {
        // Epilogue: transpose in smem -> gelu -> bf16 hi/lo (h,m,t) layout
        float* sep = (float*)smem_buf;          // [m 64][t 130]
        #pragma unroll
        for (int mi = 0; mi < 2; mi++) {
            #pragma unroll
            for (int ni = 0; ni < 4; ni++) {
                int t  = wm*32 + mi*16 + lq;
                int ml = wn*32 + ni*8 + lc*2;
                sep[ml*130 + t]          = acc[mi][ni][0];
                sep[(ml+1)*130 + t]      = acc[mi][ni][1];
                sep[ml*130 + t + 8]      = acc[mi][ni][2];
                sep[(ml+1)*130 + t + 8]  = acc[mi][ni][3];
            }
        }
        __syncthreads();
        const int ml = tid >> 2, tq = tid & 3;
        size_t dst = (size_t)h*((size_t)MM*128) + (size_t)(mt*64 + ml)*128 + tq*32;
        union P4 { __nv_bfloat16 b[4]; ull u; };
        #pragma unroll
        for (int j4 = 0; j4 < 8; j4++) {
            P4 ph, pl;
            #pragma unroll
            for (int i = 0; i < 4; i++) {
                float gv = gelu_f(sep[ml*130 + tq*32 + j4*4 + i]);
                bsplit(gv, ph.b[i], pl.b[i]);
            }
            *(ull*)(g_gh + dst + j4*4) = ph.u;
            *(ull*)(g_gl + dst + j4*4) = pl.u;
        }
    }
}

// ---------------------------------------------------------------------------
// GLU GEMM: bf16x3, 128m x 64 gemm-cols, static 48KB smem.
//   A read from (h, m, t) layout via ldmatrix.trans; one m-chunk per m-tile.
//   Fused GLU+bias+residual epilogue.
// ---------------------------------------------------------------------------
__global__ void __launch_bounds__(256) gemm_glu_kernel(int l, const float* __restrict__ bias)
{
    __shared__ __align__(128) char smem_buf[2*STG2];

    const int mch = blockIdx.y;          // m-chunk: global rows mch*128 + t
    const int nb  = blockIdx.x;
    const int tid = threadIdx.x;
    const int lane = tid & 31, w = tid >> 5;
    const int wm = w & 3;
    const int wn = w >> 2;

    const __nv_bfloat16* Whp = g_wh + (size_t)l*GN*GK;
    const __nv_bfloat16* Wlp = g_wl + (size_t)l*GN*GK;
    const __nv_bfloat16* Ahp = g_gh + (size_t)mch*128;   // + h*MM*128
    const __nv_bfloat16* Alp = g_gl + (size_t)mch*128;

    const u32 smem_base = (u32)__cvta_generic_to_shared(smem_buf);

    float acc[2][4][4];
    #pragma unroll
    for (int mi = 0; mi < 2; mi++)
        #pragma unroll
        for (int ni = 0; ni < 4; ni++)
            #pragma unroll
            for (int r = 0; r < 4; r++) acc[mi][ni][r] = 0.f;

    // A smem layout per stage: [k 32][t 128] bf16 = 32 rows x 256B, swizzle g^(k&7)
    auto load_chunk = [&](int kc, int stage) {
        int k0 = kc*32;
        u32 base = smem_base + stage*STG2;
        #pragma unroll
        for (int i = 0; i < 2; i++) {
            int gid = i*256 + tid;
            int krow = gid >> 4, g = gid & 15;
            int pg = g ^ (krow & 7);
            cp16(base + krow*256 + pg*16,
                 Ahp + (size_t)(k0 + krow)*((size_t)MM*128) + g*8);
            cp16(base + 8192 + krow*256 + pg*16,
                 Alp + (size_t)(k0 + krow)*((size_t)MM*128) + g*8);
        }
        {
            int row = tid >> 2, g = tid & 3;
            int pg = g ^ ((row >> 1) & 3);
            int wr = nb*32 + (row >> 1) + (row & 1)*256;
            cp16(base + 16384 + row*64 + pg*16, Whp + (size_t)wr*GK + k0 + g*8);
            cp16(base + 20480 + row*64 + pg*16, Wlp + (size_t)wr*GK + k0 + g*8);
        }
    };

    load_chunk(0, 0);
    asm volatile("cp.async.commit_group;");

    #pragma unroll 1
    for (int kc = 0; kc < 8; kc++) {
        if (kc + 1 < 8) load_chunk(kc + 1, (kc + 1) & 1);
        asm volatile("cp.async.commit_group;");
        asm volatile("cp.async.wait_group 1;");
        __syncthreads();

        const u32 ab  = smem_base + (kc & 1)*STG2;
        const u32 alb = ab + 8192, bhb = ab + 16384, blb = ab + 20480;

        #pragma unroll
        for (int ks = 0; ks < 2; ks++) {
            const int grp = lane >> 3, rh = lane & 7;
            // A via ldmatrix.trans from [k][t]: group -> (t-block=grp&1, k-block=grp>>1)
            u32 ah[2][4], al[2][4];
            #pragma unroll
            for (int mi = 0; mi < 2; mi++) {
                int tb   = wm*32 + mi*16;
                int krow = ks*16 + (grp >> 1)*8 + rh;
                int g    = (tb >> 3) + (grp & 1);
                u32 off  = krow*256 + ((g ^ (krow & 7))*16);
                ldsm4t(ah[mi][0], ah[mi][1], ah[mi][2], ah[mi][3], ab + off);
                ldsm4t(al[mi][0], al[mi][1], al[mi][2], al[mi][3], alb + off);
            }
            u32 bh[4][2], bl[4][2];
            #pragma unroll
            for (int nf = 0; nf < 2; nf++) {
                int row = wn*32 + nf*16 + rh + (grp >> 1)*8;
                int kg  = 2*ks + (grp & 1);
                u32 off = row*64 + ((kg ^ ((row >> 1) & 3))*16);
                u32 r0, r1, r2, r3;
                ldsm4(r0, r1, r2, r3, bhb + off);
                bh[nf*2][0] = r0; bh[nf*2][1] = r1;
                bh[nf*2+1][0] = r2; bh[nf*2+1][1] = r3;
                ldsm4(r0, r1, r2, r3, blb + off);
                bl[nf*2][0] = r0; bl[nf*2][1] = r1;
                bl[nf*2+1][0] = r2; bl[nf*2+1][1] = r3;
            }
            #pragma unroll
            for (int mi = 0; mi < 2; mi++)
                #pragma unroll
                for (int ni = 0; ni < 4; ni++) {
                    mma_bf16(acc[mi][ni], ah[mi], bh[ni]);
                    mma_bf16(acc[mi][ni], al[mi], bh[ni]);
                    mma_bf16(acc[mi][ni], ah[mi], bl[ni]);
                }
        }
        __syncthreads();
    }

    const int lc = lane & 3, lq = lane >> 2;
    const int m0 = mch*128;
    #pragma unroll
    for (int ni = 0; ni < 4; ni++) {
        const int oc = nb*32 + wn*16 + ni*4 + lc;
        const float bL = bias[oc];
        const float bR = bias[oc + 256];
        #pragma unroll
        for (int mi = 0; mi < 2; mi++) {
            int mg = m0 + wm*32 + mi*16 + lq;
            {
                float zl = acc[mi][ni][0] + bL;
                float zr_ = acc[mi][ni][1] + bR;
                float sv = zl * (1.0f/(1.0f + expf(-zr_))) + g_x[(size_t)mg*HH + oc];
                g_s[(size_t)mg*HH + oc] = sv;
            }
            {
                int mg2 = mg + 8;
                float zl = acc[mi][ni][2] + bL;
                float zr_ = acc[mi][ni][3] + bR;
                float sv = zl * (1.0f/(1.0f + expf(-zr_))) + g_x[(size_t)mg2*HH + oc];
                g_s[(size_t)mg2*HH + oc] = sv;
            }
        }
    }
}

// ---------------------------------------------------------------------------
// ln_fused: LayerNorm + (mode&1) coalesced transpose-to-X + (mode&2) heads.
// ---------------------------------------------------------------------------
__device__ __forceinline__ float softplus_f(float x) {
    return fmaxf(x, 0.f) + log1pf(expf(-fabsf(x)));
}

__global__ void __launch_bounds__(256) ln_fused_kernel(
    const float* __restrict__ lng, const float* __restrict__ lnb,
    const float* __restrict__ mu_w, const float* __restrict__ mu_b,
    const float* __restrict__ al_w, const float* __restrict__ al_b,
    float* __restrict__ out, int half, int mode)
{
    __shared__ float ysT[256][33];     // [h][t]
    const int wi = threadIdx.x >> 5, lane = threadIdx.x & 31;
    const int r0 = blockIdx.x*32;

    #pragma unroll
    for (int it = 0; it < 4; it++) {
        int rl = wi + it*8;
        size_t row = (size_t)(r0 + rl);
        const float4* sp = (const float4*)(g_s + row*HH);
        float4 v0 = sp[lane];
        float4 v1 = sp[lane + 32];

        float s1 = v0.x+v0.y+v0.z+v0.w + v1.x+v1.y+v1.z+v1.w;
        float s2 = v0.x*v0.x+v0.y*v0.y+v0.z*v0.z+v0.w*v0.w
                 + v1.x*v1.x+v1.y*v1.y+v1.z*v1.z+v1.w*v1.w;
        #pragma unroll
        for (int o = 16; o > 0; o >>= 1) {
            s1 += __shfl_xor_sync(0xffffffffu, s1, o);
            s2 += __shfl_xor_sync(0xffffffffu, s2, o);
        }
        float mean = s1 * (1.0f/HH);
        float var  = s2 * (1.0f/HH) - mean*mean;
        float inv  = rsqrtf(var + 1e-5f);

        const float4* gp = (const float4*)lng;
        const float4* bp = (const float4*)lnb;
        float4 g0 = gp[lane], g1 = gp[lane+32];
        float4 b0 = bp[lane], b1 = bp[lane+32];
        float4 y0, y1;
        y0.x = (v0.x-mean)*inv*g0.x + b0.x;  y0.y = (v0.y-mean)*inv*g0.y + b0.y;
        y0.z = (v0.z-mean)*inv*g0.z + b0.z;  y0.w = (v0.w-mean)*inv*g0.w + b0.w;
        y1.x = (v1.x-mean)*inv*g1.x + b1.x;  y1.y = (v1.y-mean)*inv*g1.y + b1.y;
        y1.z = (v1.z-mean)*inv*g1.z + b1.z;  y1.w = (v1.w-mean)*inv*g1.w + b1.w;

        float4* xp = (float4*)(g_x + row*HH);
        xp[lane] = y0;
        xp[lane + 32] = y1;

        if (mode & 1) {
            int hb0 = lane*4;
            ysT[hb0+0][rl] = y0.x; ysT[hb0+1][rl] = y0.y;
            ysT[hb0+2][rl] = y0.z; ysT[hb0+3][rl] = y0.w;
            ysT[128+hb0+0][rl] = y1.x; ysT[128+hb0+1][rl] = y1.y;
            ysT[128+hb0+2][rl] = y1.z; ysT[128+hb0+3][rl] = y1.w;
        }

        if (mode & 2) {
            const float4* mp = (const float4*)mu_w;
            const float4* ap = (const float4*)al_w;
            float4 m0 = mp[lane], m1 = mp[lane+32];
            float4 a0 = ap[lane], a1 = ap[lane+32];
            float sm = y0.x*m0.x + y0.y*m0.y + y0.z*m0.z + y0.w*m0.w
                     + y1.x*m1.x + y1.y*m1.y + y1.z*m1.z + y1.w*m1.w;
            float sa = y0.x*a0.x + y0.y*a0.y + y0.z*a0.z + y0.w*a0.w
                     + y1.x*a1.x + y1.y*a1.y + y1.z*a1.z + y1.w*a1.w;
            #pragma unroll
            for (int o = 16; o > 0; o >>= 1) {
                sm += __shfl_xor_sync(0xffffffffu, sm, o);
                sa += __shfl_xor_sync(0xffffffffu, sa, o);
            }
            if (lane == 0) {
                out[row]        = softplus_f(sm + mu_b[0]);
                out[half + row] = softplus_f(sa + al_b[0]);
            }
        }
    }

    if (mode & 1) {
        __syncthreads();
        const int m = r0 >> 7, tb = r0 & 127;
        union P4 { __nv_bfloat16 b[4]; ull u; };
        #pragma unroll
        for (int p = 0; p < 8; p++) {
            int h  = p*32 + wi*4 + (lane >> 3);
            int tq = lane & 7;
            P4 ph, pl;
            #pragma unroll
            for (int i = 0; i < 4; i++) bsplit(ysT[h][tq*4 + i], ph.b[i], pl.b[i]);
            size_t dst = (size_t)h*((size_t)MM*256) + (size_t)m*256 + tb + tq*4;
            *(ull*)(g_Xh + dst) = ph.u;
            *(ull*)(g_Xl + dst) = pl.u;
        }
    }
}

// ---------------------------------------------------------------------------
extern "C" void kernel_launch(void* const* d_in, const int* in_sizes, int n_in,
                              void* d_out, int out_size)
{
    const float* x      = (const float*)d_in[0];
    const float* enc_w  = (const float*)d_in[1];
    const float* enc_b  = (const float*)d_in[2];
    const float* log_dt = (const float*)d_in[3];
    const float* logA   = (const float*)d_in[4];
    const float* A_im   = (const float*)d_in[5];
    const float* C_re   = (const float*)d_in[6];
    const float* C_im   = (const float*)d_in[7];
    const float* Dp     = (const float*)d_in[8];
    const float* out_w  = (const float*)d_in[9];
    const float* out_b  = (const float*)d_in[10];
    const float* ln_g   = (const float*)d_in[11];
    const float* ln_b   = (const float*)d_in[12];
    const float* mu_w   = (const float*)d_in[13];
    const float* mu_b   = (const float*)d_in[14];
    const float* al_w   = (const float*)d_in[15];
    const float* al_b   = (const float*)d_in[16];
    float* out = (float*)d_out;

    enc_kernel<<<GM, HH>>>(x, enc_w, enc_b);
    wconv_kernel<<<(NLAYERS*GN*GK)/256, 256>>>(out_w);
    genG_all_kernel<<<dim3(HH, NLAYERS), 128>>>(log_dt, logA, A_im, C_re, C_im, Dp);
    fwdT_kernel<<<dim3(MM, 8), 256>>>();     // X for layer 0 only

    for (int l = 0; l < NLAYERS; l++) {
        const float* ldt = log_dt + l*HH;
        const float* lA  = logA   + (size_t)l*HH*NN;
        const float* Ai  = A_im   + (size_t)l*HH*NN;

        gemm_s4_kernel<<<dim3(4, HH), 256>>>(1, l, ldt, lA, Ai);
        gemm_s4_kernel<<<dim3(4, HH), 256>>>(2, l, ldt, lA, Ai);
        gemm_glu_kernel<<<dim3(8, GM/128), 256>>>(l, out_b + (size_t)l*GN);
        ln_fused_kernel<<<GM/32, 256>>>(ln_g + l*HH, ln_b + l*HH,
                                        mu_w, mu_b, al_w, al_b,
                                        out, out_size/2,
                                        (l == NLAYERS-1) ? 2 : 1);
    }
}

// round 15
// speedup vs baseline: 1.3854x; 1.0705x over previous
#include <cuda_runtime.h>
#include <cuda_bf16.h>
#include <math.h>

// Problem constants
#define BB 16
#define LL 2048
#define DIN 8
#define HH 256
#define NN 64
#define NLAYERS 4
#define GM (BB*LL)      // 32768 rows
#define GK HH           // 256
#define GN (2*HH)       // 512
#define NC 16           // time chunks
#define TT (LL/NC)      // 128
#define MM (BB*NC)      // 256 chunk-columns

typedef unsigned long long ull;
typedef unsigned int u32;

// Scratch (device globals)
__device__ float g_x[(size_t)GM*HH];                       // activations (row,h)
__device__ float g_s[(size_t)GM*HH];                       // pre-LN (row,h)
__device__ __nv_bfloat16 g_gh[(size_t)GM*HH];              // gelu out hi, (h,m,t) layout
__device__ __nv_bfloat16 g_gl[(size_t)GM*HH];              // gelu out lo, (h,m,t) layout
__device__ __nv_bfloat16 g_wh[(size_t)NLAYERS*GN*GK];      // GLU W hi
__device__ __nv_bfloat16 g_wl[(size_t)NLAYERS*GN*GK];      // GLU W lo
__device__ __nv_bfloat16 g_Xh[(size_t)HH*MM*256];          // X=[u;z0] hi (h,m,k)
__device__ __nv_bfloat16 g_Xl[(size_t)HH*MM*256];          // X lo
__device__ __nv_bfloat16 g_GAh[(size_t)NLAYERS*HH*128*256];// [K|V] hi (l,h,r,k)
__device__ __nv_bfloat16 g_GAl[(size_t)NLAYERS*HH*128*256];
__device__ __nv_bfloat16 g_GWh[(size_t)NLAYERS*HH*128*128];// W hi (l,h,i,s)
__device__ __nv_bfloat16 g_GWl[(size_t)NLAYERS*HH*128*128];

__device__ __forceinline__ void bsplit(float v, __nv_bfloat16& h, __nv_bfloat16& l) {
    h = __float2bfloat16_rn(v);
    l = __float2bfloat16_rn(v - __bfloat162float(h));
}

// ---------------------------------------------------------------------------
// One-shot GLU W -> bf16 hi/lo split
// ---------------------------------------------------------------------------
__global__ void wconv_kernel(const float* __restrict__ W)
{
    size_t i = (size_t)blockIdx.x*256 + threadIdx.x;
    float w = W[i];
    bsplit(w, g_wh[i], g_wl[i]);
}

// ---------------------------------------------------------------------------
__device__ __forceinline__ void s4_lambda(
    const float* log_dt, const float* logA_re, const float* A_im,
    int h, int n, float& Lr, float& Li, float& are, float& aim)
{
    float dt = expf(log_dt[h]);
    are = -expf(logA_re[h*NN + n]);
    aim = A_im[h*NN + n];
    float er = expf(dt*are);
    float dim = dt*aim;
    Lr = er*cosf(dim);
    Li = er*sinf(dim);
}

// ---------------------------------------------------------------------------
// enc_fwdT: encoder GEMV fused with the (row,h)->(h,m,t) transpose.
//   grid (MM, 8), block 256. Each block: one m-chunk x 32 h.
//   Per-thread h fixed -> enc weights in registers; x tile broadcast via smem.
//   Writes g_x (residual source) and X bf16 hi/lo (layer-0 scan input).
// ---------------------------------------------------------------------------
__global__ void __launch_bounds__(256) enc_fwdT_kernel(
    const float* __restrict__ x,
    const float* __restrict__ w,
    const float* __restrict__ b)
{
    const int m = blockIdx.x, h0 = blockIdx.y*32;
    const int bb = m >> 4, c = m & 15;
    const size_t rbase = (size_t)bb*LL + (size_t)c*TT;   // global row base
    __shared__ float xr[128][9];
    __shared__ float sT[128][33];
    const int tid = threadIdx.x;

    // load x tile: 128 rows x 8
    #pragma unroll
    for (int i = 0; i < 4; i++) {
        int gid = i*256 + tid;
        int row = gid >> 3, col = gid & 7;
        xr[row][col] = x[(rbase + row)*DIN + col];
    }
    // per-thread enc weights (h = h0 + (tid&31))
    const int hh = tid & 31;
    float wreg[DIN];
    #pragma unroll
    for (int k = 0; k < DIN; k++) wreg[k] = w[(h0 + hh)*DIN + k];
    const float breg = b[h0 + hh];
    __syncthreads();

    const int tg = tid >> 5;      // 0..7
    #pragma unroll
    for (int p = 0; p < 16; p++) {
        int t = tg*16 + p;
        float s = breg;
        #pragma unroll
        for (int k = 0; k < DIN; k++) s = fmaf(xr[t][k], wreg[k], s);
        g_x[(rbase + t)*HH + h0 + hh] = s;
        sT[t][hh] = s;
    }
    __syncthreads();

    const int wi = tid >> 5, lane = tid & 31;
    union P4 { __nv_bfloat16 b[4]; ull u; };
    #pragma unroll
    for (int p = 0; p < 4; p++) {
        int hq = p*8 + wi;
        int t0 = lane*4;
        P4 ph, pl;
        #pragma unroll
        for (int i = 0; i < 4; i++) bsplit(sT[t0+i][hq], ph.b[i], pl.b[i]);
        size_t dst = (size_t)(h0+hq)*((size_t)MM*256) + (size_t)m*256 + t0;
        *(ull*)(g_Xh + dst) = ph.u;
        *(ull*)(g_Xl + dst) = pl.u;
    }
}

// ---------------------------------------------------------------------------
// genG_all: per-(layer,channel) G_A=[K|V] (128x256), G_W (128x128), bf16 hi/lo.
// ---------------------------------------------------------------------------
__global__ void __launch_bounds__(128) genG_all_kernel(
    const float* __restrict__ log_dt_a,
    const float* __restrict__ logA_a,
    const float* __restrict__ A_im_a,
    const float* __restrict__ C_re_a,
    const float* __restrict__ C_im_a,
    const float* __restrict__ Dp_a)
{
    const int h = blockIdx.x;
    const int l = blockIdx.y;
    const int t = threadIdx.x;
    const float* log_dt = log_dt_a + l*HH;
    const float* logA_re = logA_a + (size_t)l*HH*NN;
    const float* A_im = A_im_a + (size_t)l*HH*NN;
    const float* C_re = C_re_a + (size_t)l*HH*NN;
    const float* C_im = C_im_a + (size_t)l*HH*NN;

    __shared__ float s_cr[64], s_ci[64], s_lr[64], s_li[64];
    __shared__ float s_pr[64][33], s_pi[64][33];
    __shared__ float s_k[128];

    float pr = 1.f, pi = 0.f;
    if (t < 64) {
        float are, aim, Lr, Li;
        s4_lambda(log_dt, logA_re, A_im, h, t, Lr, Li, are, aim);
        s_lr[t] = Lr; s_li[t] = Li;
        float Cre = C_re[h*NN + t], Cim = C_im[h*NN + t];
        float nr = Lr - 1.f, ni = Li;
        float tr = Cre*nr - Cim*ni, ti = Cre*ni + Cim*nr;
        float inv = 2.f/(are*are + aim*aim);
        s_cr[t] =  inv*(tr*are + ti*aim);
        s_ci[t] = -inv*(ti*are - tr*aim);
    }
    __syncthreads();
    const float Dh = Dp_a[l*HH + h];
    __nv_bfloat16* GAh = g_GAh + ((size_t)l*HH + h)*128*256;
    __nv_bfloat16* GAl = g_GAl + ((size_t)l*HH + h)*128*256;
    __nv_bfloat16* GWh = g_GWh + ((size_t)l*HH + h)*128*128;
    __nv_bfloat16* GWl = g_GWl + ((size_t)l*HH + h)*128*128;

    for (int cd = 0; cd < 4; cd++) {
        if (t < 64) {
            float Lr = s_lr[t], Li = s_li[t];
            #pragma unroll
            for (int dd = 0; dd < 32; dd++) {
                s_pr[t][dd] = pr; s_pi[t][dd] = pi;
                float npr = pr*Lr - pi*Li;
                float npi = pr*Li + pi*Lr;
                pr = npr; pi = npi;
            }
        }
        __syncthreads();
        {
            int dd = t >> 2, q = t & 3;
            float part = 0.f;
            for (int n = q*16; n < q*16 + 16; n++)
                part += s_cr[n]*s_pr[n][dd] + s_ci[n]*s_pi[n][dd];
            part += __shfl_xor_sync(0xffffffffu, part, 1);
            part += __shfl_xor_sync(0xffffffffu, part, 2);
            int d = cd*32 + dd;
            if (q == 0) s_k[d] = part + (d == 0 ? Dh : 0.f);
        }
        for (int dd = 0; dd < 32; dd++) {
            int d = cd*32 + dd, r = d - 1;
            if (r >= 0) {
                float v;
                if (t < 64)
                    v = s_cr[t]*s_pr[t][dd] + s_ci[t]*s_pi[t][dd];
                else {
                    int j = t - 64;
                    v = s_ci[j]*s_pr[j][dd] - s_cr[j]*s_pi[j][dd];
                }
                __nv_bfloat16 hb, lb; bsplit(v, hb, lb);
                GAh[r*256 + 128 + t] = hb;
                GAl[r*256 + 128 + t] = lb;
            }
        }
        for (int p = 0; p < 32; p++) {
            int row = p*4 + (t >> 5);
            int sc = t & 31;
            int s = 96 - cd*32 + sc;
            int dd = 31 - sc;
            float v = (row < 64) ? s_pr[row][dd] : s_pi[row-64][dd];
            __nv_bfloat16 hb, lb; bsplit(v, hb, lb);
            GWh[row*128 + s] = hb;
            GWl[row*128 + s] = lb;
        }
        __syncthreads();
    }
    if (t < 64) { s_pr[t][0] = pr; s_pi[t][0] = pi; }
    __syncthreads();
    {
        float v;
        if (t < 64)
            v = s_cr[t]*s_pr[t][0] + s_ci[t]*s_pi[t][0];
        else {
            int j = t - 64;
            v = s_ci[j]*s_pr[j][0] - s_cr[j]*s_pi[j][0];
        }
        __nv_bfloat16 hb, lb; bsplit(v, hb, lb);
        GAh[127*256 + 128 + t] = hb;
        GAl[127*256 + 128 + t] = lb;
    }
    for (int r = 0; r < 128; r++) {
        float v = (t <= r) ? s_k[r - t] : 0.f;
        __nv_bfloat16 hb, lb; bsplit(v, hb, lb);
        GAh[r*256 + t] = hb;
        GAl[r*256 + t] = lb;
    }
}

// ---------------------------------------------------------------------------
// GEMM building blocks
// ---------------------------------------------------------------------------
__device__ __forceinline__ void cp16(u32 dst, const void* src) {
    asm volatile("cp.async.cg.shared.global [%0], [%1], 16;" :: "r"(dst), "l"(src));
}
__device__ __forceinline__ void ldsm4(u32& r0, u32& r1, u32& r2, u32& r3, u32 addr) {
    asm volatile("ldmatrix.sync.aligned.m8n8.x4.shared.b16 {%0,%1,%2,%3},[%4];"
                 : "=r"(r0), "=r"(r1), "=r"(r2), "=r"(r3) : "r"(addr));
}
__device__ __forceinline__ void ldsm4t(u32& r0, u32& r1, u32& r2, u32& r3, u32 addr) {
    asm volatile("ldmatrix.sync.aligned.m8n8.x4.trans.shared.b16 {%0,%1,%2,%3},[%4];"
                 : "=r"(r0), "=r"(r1), "=r"(r2), "=r"(r3) : "r"(addr));
}
__device__ __forceinline__ void mma_bf16(float* d, const u32* a, const u32* b) {
    asm volatile(
        "mma.sync.aligned.m16n8k16.row.col.f32.bf16.bf16.f32 "
        "{%0,%1,%2,%3},{%4,%5,%6,%7},{%8,%9},{%0,%1,%2,%3};"
        : "+f"(d[0]), "+f"(d[1]), "+f"(d[2]), "+f"(d[3])
        : "r"(a[0]), "r"(a[1]), "r"(a[2]), "r"(a[3]), "r"(b[0]), "r"(b[1]));
}

#define STG2 24576

__device__ __forceinline__ float gelu_f(float yv) {
    return 0.5f*yv*(1.0f + erff(yv*0.70710678118654752f));
}

// ---------------------------------------------------------------------------
// gemm_s4: per-channel bf16x3.
//   pass1: Zend0 = G_W*U (K=128) -> in-block chunk composition (fused scanfix)
//          -> z0 (bf16 hi/lo) into X rows 128+  [each mt tile = 4 full batches]
//   pass2: Y = G_A*X (K=256) -> gelu -> bf16 hi/lo in (h,m,t) layout
// ---------------------------------------------------------------------------
__global__ void __launch_bounds__(256) gemm_s4_kernel(
    int pass, int l,
    const float* __restrict__ log_dt,
    const float* __restrict__ logA_re,
    const float* __restrict__ A_im)
{
    __shared__ __align__(128) char smem_buf[2*STG2];
    const int h  = blockIdx.y;
    const int mt = blockIdx.x;
    const int tid = threadIdx.x, lane = tid & 31, w = tid >> 5;
    const int wm = w & 3, wn = w >> 2;

    const int NK = (pass == 1) ? 128 : 256;
    const __nv_bfloat16* Ahp = (pass == 1) ? g_GWh + ((size_t)l*HH + h)*128*128
                                           : g_GAh + ((size_t)l*HH + h)*128*256;
    const __nv_bfloat16* Alp = (pass == 1) ? g_GWl + ((size_t)l*HH + h)*128*128
                                           : g_GAl + ((size_t)l*HH + h)*128*256;
    const __nv_bfloat16* Bhp = g_Xh + (size_t)h*MM*256;
    const __nv_bfloat16* Blp = g_Xl + (size_t)h*MM*256;

    const int nch = NK/32;
    const u32 smem_base = (u32)__cvta_generic_to_shared(smem_buf);

    float acc[2][4][4];
    #pragma unroll
    for (int mi = 0; mi < 2; mi++)
        #pragma unroll
        for (int ni = 0; ni < 4; ni++)
            #pragma unroll
            for (int r = 0; r < 4; r++) acc[mi][ni][r] = 0.f;

    auto load_chunk = [&](int kc, int stage) {
        int k0 = kc*32;
        u32 base = smem_base + stage*STG2;
        #pragma unroll
        for (int i = 0; i < 2; i++) {
            int gid = i*256 + tid;
            int row = gid >> 2, g = gid & 3;
            int pg = g ^ ((row >> 1) & 3);
            cp16(base + row*64 + pg*16,        Ahp + (size_t)row*NK + k0 + g*8);
            cp16(base + 8192 + row*64 + pg*16, Alp + (size_t)row*NK + k0 + g*8);
        }
        {
            int row = tid >> 2, g = tid & 3;
            int pg = g ^ ((row >> 1) & 3);
            cp16(base + 16384 + row*64 + pg*16, Bhp + (size_t)(mt*64 + row)*256 + k0 + g*8);
            cp16(base + 20480 + row*64 + pg*16, Blp + (size_t)(mt*64 + row)*256 + k0 + g*8);
        }
    };

    load_chunk(0, 0);
    asm volatile("cp.async.commit_group;");

    for (int kc = 0; kc < nch; kc++) {
        if (kc + 1 < nch) load_chunk(kc + 1, (kc + 1) & 1);
        asm volatile("cp.async.commit_group;");
        asm volatile("cp.async.wait_group 1;");
        __syncthreads();

        const u32 ab  = smem_base + (kc & 1)*STG2;
        const u32 alb = ab + 8192, bhb = ab + 16384, blb = ab + 20480;

        #pragma unroll
        for (int ks = 0; ks < 2; ks++) {
            const int grp = lane >> 3, rh = lane & 7;
            u32 ah[2][4], al[2][4];
            #pragma unroll
            for (int mi = 0; mi < 2; mi++) {
                int row = wm*32 + mi*16 + rh + (grp & 1)*8;
                int kg  = 2*ks + (grp >> 1);
                u32 off = row*64 + ((kg ^ ((row >> 1) & 3))*16);
                ldsm4(ah[mi][0], ah[mi][1], ah[mi][2], ah[mi][3], ab + off);
                ldsm4(al[mi][0], al[mi][1], al[mi][2], al[mi][3], alb + off);
            }
            u32 bh[4][2], bl[4][2];
            #pragma unroll
            for (int nf = 0; nf < 2; nf++) {
                int row = wn*32 + nf*16 + rh + (grp >> 1)*8;
                int kg  = 2*ks + (grp & 1);
                u32 off = row*64 + ((kg ^ ((row >> 1) & 3))*16);
                u32 r0, r1, r2, r3;
                ldsm4(r0, r1, r2, r3, bhb + off);
                bh[nf*2][0] = r0; bh[nf*2][1] = r1;
                bh[nf*2+1][0] = r2; bh[nf*2+1][1] = r3;
                ldsm4(r0, r1, r2, r3, blb + off);
                bl[nf*2][0] = r0; bl[nf*2][1] = r1;
                bl[nf*2+1][0] = r2; bl[nf*2+1][1] = r3;
            }
            #pragma unroll
            for (int mi = 0; mi < 2; mi++)
                #pragma unroll
                for (int ni = 0; ni < 4; ni++) {
                    mma_bf16(acc[mi][ni], ah[mi], bh[ni]);
                    mma_bf16(acc[mi][ni], al[mi], bh[ni]);
                    mma_bf16(acc[mi][ni], ah[mi], bl[ni]);
                }
        }
        __syncthreads();
    }

    const int lq = lane >> 2, lc = lane & 3;
    if (pass == 1) {
        // Fused scanfix: stage Zend0 [128 rows][64 m] in smem, compose per (n,b).
        float* sepz = (float*)smem_buf;       // [128][68]
        #pragma unroll
        for (int mi = 0; mi < 2; mi++) {
            #pragma unroll
            for (int ni = 0; ni < 4; ni++) {
                int row = wm*32 + mi*16 + lq;
                int col = wn*32 + ni*8 + lc*2;
                sepz[row*68 + col]       = acc[mi][ni][0];
                sepz[row*68 + col + 1]   = acc[mi][ni][1];
                sepz[(row+8)*68 + col]   = acc[mi][ni][2];
                sepz[(row+8)*68 + col+1] = acc[mi][ni][3];
            }
        }
        __syncthreads();

        const int n = tid & 63, bloc = tid >> 6;      // 4 batches per mt tile
        float Lr, Li, are, aim;
        s4_lambda(log_dt, logA_re, A_im, h, n, Lr, Li, are, aim);
        #pragma unroll
        for (int s = 0; s < 7; s++) {                 // lambda^128
            float nr2 = Lr*Lr - Li*Li, ni2 = 2.f*Lr*Li;
            Lr = nr2; Li = ni2;
        }
        __nv_bfloat16* Xh = g_Xh + (size_t)h*MM*256;
        __nv_bfloat16* Xl = g_Xl + (size_t)h*MM*256;
        float cr = 0.f, ci = 0.f;
        #pragma unroll
        for (int c = 0; c < NC; c++) {
            int mloc = bloc*16 + c;
            size_t mg = (size_t)(mt*64 + mloc);
            __nv_bfloat16 hb, lb;
            bsplit(cr, hb, lb);
            Xh[mg*256 + 128 + n] = hb; Xl[mg*256 + 128 + n] = lb;
            bsplit(ci, hb, lb);
            Xh[mg*256 + 192 + n] = hb; Xl[mg*256 + 192 + n] = lb;
            float zr = sepz[n*68 + mloc];
            float zi = sepz[(n+64)*68 + mloc];
            float nr2 = Lr*cr - Li*ci + zr;
            float ni2 = Lr*ci + Li*cr + zi;
            cr = nr2; ci = ni2;
        }
    } else {
        // Epilogue: transpose in smem -> gelu -> bf16 hi/lo (h,m,t) layout
        float* sep = (float*)smem_buf;          // [m 64][t 130]
        #pragma unroll
        for (int mi = 0; mi < 2; mi++) {
            #pragma unroll
            for (int ni = 0; ni < 4; ni++) {
                int t  = wm*32 + mi*16 + lq;
                int ml = wn*32 + ni*8 + lc*2;
                sep[ml*130 + t]          = acc[mi][ni][0];
                sep[(ml+1)*130 + t]      = acc[mi][ni][1];
                sep[ml*130 + t + 8]      = acc[mi][ni][2];
                sep[(ml+1)*130 + t + 8]  = acc[mi][ni][3];
            }
        }
        __syncthreads();
        const int ml = tid >> 2, tq = tid & 3;
        size_t dst = (size_t)h*((size_t)MM*128) + (size_t)(mt*64 + ml)*128 + tq*32;
        union P4 { __nv_bfloat16 b[4]; ull u; };
        #pragma unroll
        for (int j4 = 0; j4 < 8; j4++) {
            P4 ph, pl;
            #pragma unroll
            for (int i = 0; i < 4; i++) {
                float gv = gelu_f(sep[ml*130 + tq*32 + j4*4 + i]);
                bsplit(gv, ph.b[i], pl.b[i]);
            }
            *(ull*)(g_gh + dst + j4*4) = ph.u;
            *(ull*)(g_gl + dst + j4*4) = pl.u;
        }
    }
}

// ---------------------------------------------------------------------------
// GLU GEMM: bf16x3, 128m x 128 gemm-cols (64 GLU pairs), 64KB dynamic smem.
//   A from (h,m,t) layout via ldmatrix.trans; B two-phase (hi then lo) to cap
//   registers. 8 warps = 4m x 2n; warp tile 32m x 64n.
//   Stage: A_h 0 | A_l 8K | B_h 16K | B_l 24K; stride 32K.
// ---------------------------------------------------------------------------
#define GSTG3 32768
#define GLU_SMEM (2*GSTG3)

__global__ void __launch_bounds__(256, 2) gemm_glu_kernel(int l, const float* __restrict__ bias)
{
    extern __shared__ __align__(128) char smem_buf[];

    const int mch = blockIdx.y;          // m-chunk: global rows mch*128 + t
    const int nb  = blockIdx.x;          // 0..3 (64 GLU pairs each)
    const int tid = threadIdx.x;
    const int lane = tid & 31, w = tid >> 5;
    const int wm = w & 3;
    const int wn = w >> 2;

    const __nv_bfloat16* Whp = g_wh + (size_t)l*GN*GK;
    const __nv_bfloat16* Wlp = g_wl + (size_t)l*GN*GK;
    const __nv_bfloat16* Ahp = g_gh + (size_t)mch*128;   // + h*MM*128
    const __nv_bfloat16* Alp = g_gl + (size_t)mch*128;

    const u32 smem_base = (u32)__cvta_generic_to_shared(smem_buf);

    float acc[2][8][4];
    #pragma unroll
    for (int mi = 0; mi < 2; mi++)
        #pragma unroll
        for (int ni = 0; ni < 8; ni++)
            #pragma unroll
            for (int r = 0; r < 4; r++) acc[mi][ni][r] = 0.f;

    // A smem per stage: [k 32][t 128] bf16, swizzle g^(k&7). B: 128 rows x 32k.
    auto load_chunk = [&](int kc, int stage) {
        int k0 = kc*32;
        u32 base = smem_base + stage*GSTG3;
        #pragma unroll
        for (int i = 0; i < 2; i++) {
            int gid = i*256 + tid;
            int krow = gid >> 4, g = gid & 15;
            int pg = g ^ (krow & 7);
            cp16(base + krow*256 + pg*16,
                 Ahp + (size_t)(k0 + krow)*((size_t)MM*128) + g*8);
            cp16(base + 8192 + krow*256 + pg*16,
                 Alp + (size_t)(k0 + krow)*((size_t)MM*128) + g*8);
        }
        #pragma unroll
        for (int i = 0; i < 2; i++) {
            int gid = i*256 + tid;
            int row = gid >> 2, g = gid & 3;
            int pg = g ^ ((row >> 1) & 3);
            int wr = nb*64 + (row >> 1) + (row & 1)*256;
            cp16(base + 16384 + row*64 + pg*16, Whp + (size_t)wr*GK + k0 + g*8);
            cp16(base + 24576 + row*64 + pg*16, Wlp + (size_t)wr*GK + k0 + g*8);
        }
    };

    load_chunk(0, 0);
    asm volatile("cp.async.commit_group;");

    #pragma unroll 1
    for (int kc = 0; kc < 8; kc++) {
        if (kc + 1 < 8) load_chunk(kc + 1, (kc + 1) & 1);
        asm volatile("cp.async.commit_group;");
        asm volatile("cp.async.wait_group 1;");
        __syncthreads();

        const u32 ab  = smem_base + (kc & 1)*GSTG3;
        const u32 alb = ab + 8192, bhb = ab + 16384, blb = ab + 24576;

        #pragma unroll
        for (int ks = 0; ks < 2; ks++) {
            const int grp = lane >> 3, rh = lane & 7;
            u32 ah[2][4], al[2][4];
            #pragma unroll
            for (int mi = 0; mi < 2; mi++) {
                int tb   = wm*32 + mi*16;
                int krow = ks*16 + (grp >> 1)*8 + rh;
                int g    = (tb >> 3) + (grp & 1);
                u32 off  = krow*256 + ((g ^ (krow & 7))*16);
                ldsm4t(ah[mi][0], ah[mi][1], ah[mi][2], ah[mi][3], ab + off);
                ldsm4t(al[mi][0], al[mi][1], al[mi][2], al[mi][3], alb + off);
            }
            // B: hi phase (2 mma combos), then lo phase (1 combo)
            u32 bfr[8][2];
            #pragma unroll
            for (int nf = 0; nf < 4; nf++) {
                int row = wn*64 + nf*16 + rh + (grp >> 1)*8;
                int kg  = 2*ks + (grp & 1);
                u32 off = row*64 + ((kg ^ ((row >> 1) & 3))*16);
                u32 r0, r1, r2, r3;
                ldsm4(r0, r1, r2, r3, bhb + off);
                bfr[nf*2][0] = r0; bfr[nf*2][1] = r1;
                bfr[nf*2+1][0] = r2; bfr[nf*2+1][1] = r3;
            }
            #pragma unroll
            for (int mi = 0; mi < 2; mi++)
                #pragma unroll
                for (int ni = 0; ni < 8; ni++) {
                    mma_bf16(acc[mi][ni], ah[mi], bfr[ni]);
                    mma_bf16(acc[mi][ni], al[mi], bfr[ni]);
                }
            #pragma unroll
            for (int nf = 0; nf < 4; nf++) {
                int row = wn*64 + nf*16 + rh + (grp >> 1)*8;
                int kg  = 2*ks + (grp & 1);
                u32 off = row*64 + ((kg ^ ((row >> 1) & 3))*16);
                u32 r0, r1, r2, r3;
                ldsm4(r0, r1, r2, r3, blb + off);
                bfr[nf*2][0] = r0; bfr[nf*2][1] = r1;
                bfr[nf*2+1][0] = r2; bfr[nf*2+1][1] = r3;
            }
            #pragma unroll
            for (int mi = 0; mi < 2; mi++)
                #pragma unroll
                for (int ni = 0; ni < 8; ni++)
                    mma_bf16(acc[mi][ni], ah[mi], bfr[ni]);
        }
        __syncthreads();
    }

    const int lc = lane & 3, lq = lane >> 2;
    const int m0 = mch*128;
    #pragma unroll
    for (int ni = 0; ni < 8; ni++) {
        const int oc = nb*64 + wn*32 + ni*4 + lc;
        const float bL = bias[oc];
        const float bR = bias[oc + 256];
        #pragma unroll
        for (int mi = 0; mi < 2; mi++) {
            int mg = m0 + wm*32 + mi*16 + lq;
            {
                float zl = acc[mi][ni][0] + bL;
                float zr_ = acc[mi][ni][1] + bR;
                float sv = zl * (1.0f/(1.0f + expf(-zr_))) + g_x[(size_t)mg*HH + oc];
                g_s[(size_t)mg*HH + oc] = sv;
            }
            {
                int mg2 = mg + 8;
                float zl = acc[mi][ni][2] + bL;
                float zr_ = acc[mi][ni][3] + bR;
                float sv = zl * (1.0f/(1.0f + expf(-zr_))) + g_x[(size_t)mg2*HH + oc];
                g_s[(size_t)mg2*HH + oc] = sv;
            }
        }
    }
}

// ---------------------------------------------------------------------------
// ln_fused: LayerNorm + (mode&1) coalesced transpose-to-X + (mode&2) heads.
// ---------------------------------------------------------------------------
__device__ __forceinline__ float softplus_f(float x) {
    return fmaxf(x, 0.f) + log1pf(expf(-fabsf(x)));
}

__global__ void __launch_bounds__(256) ln_fused_kernel(
    const float* __restrict__ lng, const float* __restrict__ lnb,
    const float* __restrict__ mu_w, const float* __restrict__ mu_b,
    const float* __restrict__ al_w, const float* __restrict__ al_b,
    float* __restrict__ out, int half, int mode)
{
    __shared__ float ysT[256][33];     // [h][t]
    const int wi = threadIdx.x >> 5, lane = threadIdx.x & 31;
    const int r0 = blockIdx.x*32;

    #pragma unroll
    for (int it = 0; it < 4; it++) {
        int rl = wi + it*8;
        size_t row = (size_t)(r0 + rl);
        const float4* sp = (const float4*)(g_s + row*HH);
        float4 v0 = sp[lane];
        float4 v1 = sp[lane + 32];

        float s1 = v0.x+v0.y+v0.z+v0.w + v1.x+v1.y+v1.z+v1.w;
        float s2 = v0.x*v0.x+v0.y*v0.y+v0.z*v0.z+v0.w*v0.w
                 + v1.x*v1.x+v1.y*v1.y+v1.z*v1.z+v1.w*v1.w;
        #pragma unroll
        for (int o = 16; o > 0; o >>= 1) {
            s1 += __shfl_xor_sync(0xffffffffu, s1, o);
            s2 += __shfl_xor_sync(0xffffffffu, s2, o);
        }
        float mean = s1 * (1.0f/HH);
        float var  = s2 * (1.0f/HH) - mean*mean;
        float inv  = rsqrtf(var + 1e-5f);

        const float4* gp = (const float4*)lng;
        const float4* bp = (const float4*)lnb;
        float4 g0 = gp[lane], g1 = gp[lane+32];
        float4 b0 = bp[lane], b1 = bp[lane+32];
        float4 y0, y1;
        y0.x = (v0.x-mean)*inv*g0.x + b0.x;  y0.y = (v0.y-mean)*inv*g0.y + b0.y;
        y0.z = (v0.z-mean)*inv*g0.z + b0.z;  y0.w = (v0.w-mean)*inv*g0.w + b0.w;
        y1.x = (v1.x-mean)*inv*g1.x + b1.x;  y1.y = (v1.y-mean)*inv*g1.y + b1.y;
        y1.z = (v1.z-mean)*inv*g1.z + b1.z;  y1.w = (v1.w-mean)*inv*g1.w + b1.w;

        float4* xp = (float4*)(g_x + row*HH);
        xp[lane] = y0;
        xp[lane + 32] = y1;

        if (mode & 1) {
            int hb0 = lane*4;
            ysT[hb0+0][rl] = y0.x; ysT[hb0+1][rl] = y0.y;
            ysT[hb0+2][rl] = y0.z; ysT[hb0+3][rl] = y0.w;
            ysT[128+hb0+0][rl] = y1.x; ysT[128+hb0+1][rl] = y1.y;
            ysT[128+hb0+2][rl] = y1.z; ysT[128+hb0+3][rl] = y1.w;
        }

        if (mode & 2) {
            const float4* mp = (const float4*)mu_w;
            const float4* ap = (const float4*)al_w;
            float4 m0 = mp[lane], m1 = mp[lane+32];
            float4 a0 = ap[lane], a1 = ap[lane+32];
            float sm = y0.x*m0.x + y0.y*m0.y + y0.z*m0.z + y0.w*m0.w
                     + y1.x*m1.x + y1.y*m1.y + y1.z*m1.z + y1.w*m1.w;
            float sa = y0.x*a0.x + y0.y*a0.y + y0.z*a0.z + y0.w*a0.w
                     + y1.x*a1.x + y1.y*a1.y + y1.z*a1.z + y1.w*a1.w;
            #pragma unroll
            for (int o = 16; o > 0; o >>= 1) {
                sm += __shfl_xor_sync(0xffffffffu, sm, o);
                sa += __shfl_xor_sync(0xffffffffu, sa, o);
            }
            if (lane == 0) {
                out[row]        = softplus_f(sm + mu_b[0]);
                out[half + row] = softplus_f(sa + al_b[0]);
            }
        }
    }

    if (mode & 1) {
        __syncthreads();
        const int m = r0 >> 7, tb = r0 & 127;
        union P4 { __nv_bfloat16 b[4]; ull u; };
        #pragma unroll
        for (int p = 0; p < 8; p++) {
            int h  = p*32 + wi*4 + (lane >> 3);
            int tq = lane & 7;
            P4 ph, pl;
            #pragma unroll
            for (int i = 0; i < 4; i++) bsplit(ysT[h][tq*4 + i], ph.b[i], pl.b[i]);
            size_t dst = (size_t)h*((size_t)MM*256) + (size_t)m*256 + tb + tq*4;
            *(ull*)(g_Xh + dst) = ph.u;
            *(ull*)(g_Xl + dst) = pl.u;
        }
    }
}

// ---------------------------------------------------------------------------
extern "C" void kernel_launch(void* const* d_in, const int* in_sizes, int n_in,
                              void* d_out, int out_size)
{
    const float* x      = (const float*)d_in[0];
    const float* enc_w  = (const float*)d_in[1];
    const float* enc_b  = (const float*)d_in[2];
    const float* log_dt = (const float*)d_in[3];
    const float* logA   = (const float*)d_in[4];
    const float* A_im   = (const float*)d_in[5];
    const float* C_re   = (const float*)d_in[6];
    const float* C_im   = (const float*)d_in[7];
    const float* Dp     = (const float*)d_in[8];
    const float* out_w  = (const float*)d_in[9];
    const float* out_b  = (const float*)d_in[10];
    const float* ln_g   = (const float*)d_in[11];
    const float* ln_b   = (const float*)d_in[12];
    const float* mu_w   = (const float*)d_in[13];
    const float* mu_b   = (const float*)d_in[14];
    const float* al_w   = (const float*)d_in[15];
    const float* al_b   = (const float*)d_in[16];
    float* out = (float*)d_out;

    cudaFuncSetAttribute(gemm_glu_kernel,
                         cudaFuncAttributeMaxDynamicSharedMemorySize, GLU_SMEM);

    enc_fwdT_kernel<<<dim3(MM, 8), 256>>>(x, enc_w, enc_b);
    wconv_kernel<<<(NLAYERS*GN*GK)/256, 256>>>(out_w);
    genG_all_kernel<<<dim3(HH, NLAYERS), 128>>>(log_dt, logA, A_im, C_re, C_im, Dp);

    for (int l = 0; l < NLAYERS; l++) {
        const float* ldt = log_dt + l*HH;
        const float* lA  = logA   + (size_t)l*HH*NN;
        const float* Ai  = A_im   + (size_t)l*HH*NN;

        gemm_s4_kernel<<<dim3(4, HH), 256>>>(1, l, ldt, lA, Ai);
        gemm_s4_kernel<<<dim3(4, HH), 256>>>(2, l, ldt, lA, Ai);
        gemm_glu_kernel<<<dim3(4, GM/128), 256, GLU_SMEM>>>(l, out_b + (size_t)l*GN);
        ln_fused_kernel<<<GM/32, 256>>>(ln_g + l*HH, ln_b + l*HH,
                                        mu_w, mu_b, al_w, al_b,
                                        out, out_size/2,
                                        (l == NLAYERS-1) ? 2 : 1);
    }
}